// round 14
// baseline (speedup 1.0000x reference)
#include <cuda_runtime.h>
#include <cuda_bf16.h>
#include <cstdint>

#define N_NODES 50000
#define N_EDGES 800000
#define DIM     128

#define TILE_M   64
#define N_TILES  ((N_NODES + TILE_M - 1) / TILE_M)   // 782

// ---------------- SMEM layout (bytes, dynamic) ----------------------------
#define OFF_XHI   0
#define OFF_XLO   16384
#define OFF_WHI   32768
#define OFF_WLO   65536
#define OFF_CONST 98304                  // bias/scale/offset: 3 x 512B
#define GEMM_SMEM (98304 + 1536)
#define STAGE_STRIDE 132                 // fp32 stage [64][132] overlays X tiles

// ---------------- scan partition ------------------------------------------
#define SCAN_BS   256
#define NB_SCAN   ((N_NODES + SCAN_BS - 1) / SCAN_BS)   // 196

// ---------------- scratch (__device__ globals; zero-initialized) ----------
__device__ int   g_cnt[N_NODES];                      // self-cleaned each call
__device__ int   g_ofs[N_NODES + 1];
__device__ int   g_cur[N_NODES];
__device__ int2  g_pack[N_EDGES];                     // (col, val bits)
__device__ unsigned long long g_state[NB_SCAN];       // lookback: (flag<<32)|sum
// pre-swizzled bf16 tiles
__device__ __align__(16) char g_wshi[32768];
__device__ __align__(16) char g_wslo[32768];
__device__ __align__(16) char g_wnhi[32768];
__device__ __align__(16) char g_wnlo[32768];
__device__ __align__(16) char g_xhi[(size_t)N_TILES * 16384];   // 12.8MB
__device__ __align__(16) char g_xlo[(size_t)N_TILES * 16384];

// ---------------------------------------------------------------------------
// count: int4 edge loads, 4 REDs per thread (MLP=4)
// ---------------------------------------------------------------------------
__global__ void count_kernel(const int4* __restrict__ erow4, int* __restrict__ cnt) {
    int e = blockIdx.x * blockDim.x + threadIdx.x;
    if (e < N_EDGES / 4) {
        int4 r = erow4[e];
        atomicAdd(&cnt[r.x], 1);
        atomicAdd(&cnt[r.y], 1);
        atomicAdd(&cnt[r.z], 1);
        atomicAdd(&cnt[r.w], 1);
    }
}

// ---------------------------------------------------------------------------
// single-pass exclusive scan with decoupled lookback (196 blocks, all resident)
// cnt is self-cleaned (read then zeroed) so the next graph replay sees zeros.
// g_state reset by fill_kernel after use.
// ---------------------------------------------------------------------------
__global__ void __launch_bounds__(SCAN_BS) scan_offsets_kernel(
    int* __restrict__ cnt, int* __restrict__ ofs, int* __restrict__ cur)
{
    __shared__ int sh[SCAN_BS];
    __shared__ int s_prefix;
    const int t = threadIdx.x;
    const int b = blockIdx.x;
    const int i = b * SCAN_BS + t;
    int v = (i < N_NODES) ? cnt[i] : 0;
    if (i < N_NODES) cnt[i] = 0;          // self-clean for next replay
    sh[t] = v;
    __syncthreads();
#pragma unroll
    for (int o = 1; o < SCAN_BS; o <<= 1) {
        int u = (t >= o) ? sh[t - o] : 0;
        __syncthreads();
        sh[t] += u;
        __syncthreads();
    }
    const int total = sh[SCAN_BS - 1];

    if (t == 0) {
        if (b == 0) {
            atomicExch(&g_state[0], (2ull << 32) | (unsigned)total);
            s_prefix = 0;
        } else {
            atomicExch(&g_state[b], (1ull << 32) | (unsigned)total);
            int prefix = 0;
            for (int j = b - 1; j >= 0; ) {
                unsigned long long st;
                do { st = atomicAdd(&g_state[j], 0ull); } while ((st >> 32) == 0ull);
                prefix += (int)(unsigned)st;
                if ((st >> 32) == 2ull) break;
                j--;
            }
            atomicExch(&g_state[b], (2ull << 32) | (unsigned)(prefix + total));
            s_prefix = prefix;
        }
    }
    __syncthreads();

    const int excl = s_prefix + sh[t] - v;
    if (i < N_NODES) { ofs[i] = excl; cur[i] = excl; }
    if (i == N_NODES - 1) ofs[N_NODES] = N_EDGES;
}

__global__ void fill_kernel(const int* __restrict__ erow, const int* __restrict__ ecol,
                            const float* __restrict__ eval_,
                            int* __restrict__ cur, int2* __restrict__ pack) {
    int e = blockIdx.x * blockDim.x + threadIdx.x;
    if (e < NB_SCAN) g_state[e] = 0ull;   // reset lookback state for next replay
    if (e >= N_EDGES) return;
    int p = atomicAdd(&cur[erow[e]], 1);
    pack[p] = make_int2(ecol[e], __float_as_int(eval_[e]));
}

// ---------------------------------------------------------------------------
__device__ __forceinline__ uint32_t bt_off(int r, int k0) {
    return (uint32_t)(r * 256 + ((((k0 >> 3) ^ (r & 7)) & 15) << 4));
}
__device__ __forceinline__ void split_store8(const float* src, char* hi_base, char* lo_base,
                                             int r, int k0) {
    float4 a = ((const float4*)src)[0];
    float4 b = ((const float4*)src)[1];
    float v[8] = {a.x, a.y, a.z, a.w, b.x, b.y, b.z, b.w};
    uint32_t hp[4], lp[4];
#pragma unroll
    for (int e = 0; e < 4; e++) {
        __nv_bfloat16 h0 = __float2bfloat16(v[2 * e]);
        __nv_bfloat16 h1 = __float2bfloat16(v[2 * e + 1]);
        __nv_bfloat16 l0 = __float2bfloat16(v[2 * e]     - __bfloat162float(h0));
        __nv_bfloat16 l1 = __float2bfloat16(v[2 * e + 1] - __bfloat162float(h1));
        __nv_bfloat162 hh = __halves2bfloat162(h0, h1);
        __nv_bfloat162 ll = __halves2bfloat162(l0, l1);
        hp[e] = *(uint32_t*)&hh;
        lp[e] = *(uint32_t*)&ll;
    }
    uint32_t o = bt_off(r, k0);
    *(uint4*)(hi_base + o) = make_uint4(hp[0], hp[1], hp[2], hp[3]);
    *(uint4*)(lo_base + o) = make_uint4(lp[0], lp[1], lp[2], lp[3]);
}

// one-shot W conversion -> pre-swizzled bf16 hi/lo global tiles
__global__ void __launch_bounds__(256) wconv_kernel(const float* __restrict__ Ws,
                                                    const float* __restrict__ Wn) {
    int i = blockIdx.x * blockDim.x + threadIdx.x;   // 0..4095
    if (i >= 4096) return;
    int sel = i >> 11;
    int j   = i & 2047;
    int r = j >> 4, k0 = (j & 15) << 3;
    const float* W = sel ? Wn : Ws;
    char* hi = sel ? g_wnhi : g_wshi;
    char* lo = sel ? g_wnlo : g_wslo;
    split_store8(W + r * DIM + k0, hi, lo, r, k0);
}

// ---------------------------------------------------------------------------
// gather: WARP per node, lane = float4 of 4 dims, unroll x8; writes bf16 hi/lo
// directly in the per-tile swizzled layout the neigh GEMM consumes.
// ---------------------------------------------------------------------------
__global__ void __launch_bounds__(256, 4) gather_kernel(
    const float4* __restrict__ feat4, const int* __restrict__ ofs,
    const int2* __restrict__ pack)
{
    const int node = (blockIdx.x * blockDim.x + threadIdx.x) >> 5;
    const int lane = threadIdx.x & 31;
    if (node >= N_TILES * TILE_M) return;

    float4 acc = make_float4(0.f, 0.f, 0.f, 0.f);
    if (node < N_NODES) {
        const int beg = ofs[node];
        const int end = ofs[node + 1];
        int e = beg;
        for (; e + 8 <= end; e += 8) {
            int2 p[8];
            float4 x[8];
#pragma unroll
            for (int i = 0; i < 8; i++) p[i] = pack[e + i];
#pragma unroll
            for (int i = 0; i < 8; i++) x[i] = feat4[(size_t)p[i].x * 32 + lane];
#pragma unroll
            for (int i = 0; i < 8; i++) {
                float v = __int_as_float(p[i].y);
                acc.x = fmaf(v, x[i].x, acc.x); acc.y = fmaf(v, x[i].y, acc.y);
                acc.z = fmaf(v, x[i].z, acc.z); acc.w = fmaf(v, x[i].w, acc.w);
            }
        }
        for (; e + 4 <= end; e += 4) {
            int2 p[4];
            float4 x[4];
#pragma unroll
            for (int i = 0; i < 4; i++) p[i] = pack[e + i];
#pragma unroll
            for (int i = 0; i < 4; i++) x[i] = feat4[(size_t)p[i].x * 32 + lane];
#pragma unroll
            for (int i = 0; i < 4; i++) {
                float v = __int_as_float(p[i].y);
                acc.x = fmaf(v, x[i].x, acc.x); acc.y = fmaf(v, x[i].y, acc.y);
                acc.z = fmaf(v, x[i].z, acc.z); acc.w = fmaf(v, x[i].w, acc.w);
            }
        }
        for (; e < end; e++) {
            int2 p = pack[e];
            float v = __int_as_float(p.y);
            float4 x = feat4[(size_t)p.x * 32 + lane];
            acc.x = fmaf(v, x.x, acc.x); acc.y = fmaf(v, x.y, acc.y);
            acc.z = fmaf(v, x.z, acc.z); acc.w = fmaf(v, x.w, acc.w);
        }
    }

    __nv_bfloat16 h0 = __float2bfloat16(acc.x), h1 = __float2bfloat16(acc.y);
    __nv_bfloat16 h2 = __float2bfloat16(acc.z), h3 = __float2bfloat16(acc.w);
    __nv_bfloat16 l0 = __float2bfloat16(acc.x - __bfloat162float(h0));
    __nv_bfloat16 l1 = __float2bfloat16(acc.y - __bfloat162float(h1));
    __nv_bfloat16 l2 = __float2bfloat16(acc.z - __bfloat162float(h2));
    __nv_bfloat16 l3 = __float2bfloat16(acc.w - __bfloat162float(h3));
    __nv_bfloat162 hA = __halves2bfloat162(h0, h1), hB = __halves2bfloat162(h2, h3);
    __nv_bfloat162 lA = __halves2bfloat162(l0, l1), lB = __halves2bfloat162(l2, l3);

    const int tile = node >> 6, r = node & 63;
    const uint32_t off = (uint32_t)r * 256
                       + ((((lane >> 1) ^ (r & 7)) & 15) << 4) + ((lane & 1) << 3);
    char* hb = g_xhi + (size_t)tile * 16384;
    char* lb = g_xlo + (size_t)tile * 16384;
    *(uint2*)(hb + off) = make_uint2(*(uint32_t*)&hA, *(uint32_t*)&hB);
    *(uint2*)(lb + off) = make_uint2(*(uint32_t*)&lA, *(uint32_t*)&lB);
}

// ---------------------------------------------------------------------------
__device__ __forceinline__ uint32_t smem_u32(const void* p) {
    uint32_t a;
    asm("{ .reg .u64 t; cvta.to.shared.u64 t, %1; cvt.u32.u64 %0, t; }" : "=r"(a) : "l"(p));
    return a;
}
__device__ __forceinline__ void ldsm_x4(uint32_t& r0, uint32_t& r1,
                                        uint32_t& r2, uint32_t& r3, uint32_t a) {
    asm volatile("ldmatrix.sync.aligned.m8n8.x4.shared.b16 {%0,%1,%2,%3}, [%4];"
                 : "=r"(r0), "=r"(r1), "=r"(r2), "=r"(r3) : "r"(a));
}
__device__ __forceinline__ void mma_bf16(float* c, const uint32_t* a,
                                         uint32_t b0, uint32_t b1) {
    asm volatile("mma.sync.aligned.m16n8k16.row.col.f32.bf16.bf16.f32 "
                 "{%0,%1,%2,%3}, {%4,%5,%6,%7}, {%8,%9}, {%0,%1,%2,%3};"
                 : "+f"(c[0]), "+f"(c[1]), "+f"(c[2]), "+f"(c[3])
                 : "r"(a[0]), "r"(a[1]), "r"(a[2]), "r"(a[3]), "r"(b0), "r"(b1));
}
__device__ __forceinline__ uint32_t a_addr(uint32_t base, int m0, int kb, int lane) {
    int row = m0 + (lane & 15);
    int chunk = (kb >> 3) + (lane >> 4);
    return base + row * 256 + (((chunk ^ (row & 7)) & 15) << 4);
}
__device__ __forceinline__ uint32_t b_addr(uint32_t base, int n0, int kb, int lane) {
    int row = n0 + (lane & 7) + ((lane >> 4) << 3);
    int chunk = (kb >> 3) + ((lane >> 3) & 1);
    return base + row * 256 + (((chunk ^ (row & 7)) & 15) << 4);
}

// ---------------------------------------------------------------------------
// Tensor branch (mma.sync bf16 3-term split), TILE_M=64, 2 CTAs/SM.
// MODE 0 (self): X = feat_in (converted in-kernel), no accumulate.
// MODE 1 (neigh): X = pre-swizzled bf16 tiles from gather; accumulate.
// ---------------------------------------------------------------------------
template<int MODE>
__global__ void __launch_bounds__(256, 2) mma_branch(
    const float* __restrict__ X,
    const uint4* __restrict__ gwhi, const uint4* __restrict__ gwlo,
    const uint4* __restrict__ gxhi, const uint4* __restrict__ gxlo,
    const float* __restrict__ bias, const float* __restrict__ scale,
    const float* __restrict__ offset, int so, float* __restrict__ out)
{
    extern __shared__ char smem[];
    const uint32_t sb = smem_u32(smem);
    const int tid  = threadIdx.x;
    const int wid  = tid >> 5;
    const int lane = tid & 31;
    const int mw   = wid & 1;
    const int nw   = wid >> 1;
    const int gbase = blockIdx.x * TILE_M;

    for (int i = tid; i < 2048; i += 256) {
        ((uint4*)(smem + OFF_WHI))[i] = gwhi[i];
        ((uint4*)(smem + OFF_WLO))[i] = gwlo[i];
    }
    if (MODE == 0) {
        for (int i = tid; i < 1024; i += 256) {
            int r = i >> 4, k0 = (i & 15) << 3;
            int gr = gbase + r; if (gr >= N_NODES) gr = N_NODES - 1;
            split_store8(X + (size_t)gr * DIM + k0, smem + OFF_XHI, smem + OFF_XLO, r, k0);
        }
    } else {
        const uint4* xh = gxhi + (size_t)blockIdx.x * 1024;
        const uint4* xl = gxlo + (size_t)blockIdx.x * 1024;
        for (int i = tid; i < 1024; i += 256) {
            ((uint4*)(smem + OFF_XHI))[i] = xh[i];
            ((uint4*)(smem + OFF_XLO))[i] = xl[i];
        }
    }
    float* sB = (float*)(smem + OFF_CONST);
    float* sS = sB + 128;
    float* sO = sS + 128;
    if (tid < 32)       ((float4*)sB)[tid]      = ((const float4*)bias)[tid];
    else if (tid < 64)  ((float4*)sS)[tid - 32] = ((const float4*)(scale  + so))[tid - 32];
    else if (tid < 96)  ((float4*)sO)[tid - 64] = ((const float4*)(offset + so))[tid - 64];
    __syncthreads();

    float acc[2][4][4];
#pragma unroll
    for (int mt = 0; mt < 2; mt++)
#pragma unroll
        for (int nt = 0; nt < 4; nt++)
#pragma unroll
            for (int e = 0; e < 4; e++) acc[mt][nt][e] = 0.f;

    const uint32_t xhi = sb + OFF_XHI, xlo = sb + OFF_XLO;
    const uint32_t whi = sb + OFF_WHI, wlo = sb + OFF_WLO;

#pragma unroll
    for (int kb8 = 0; kb8 < 8; kb8++) {
        const int kb = kb8 * 16;
        uint32_t ahi[2][4], alo[2][4], bhi[4][2], blo[4][2];
#pragma unroll
        for (int mt = 0; mt < 2; mt++) {
            uint32_t aa = a_addr(xhi, mw * 32 + mt * 16, kb, lane);
            ldsm_x4(ahi[mt][0], ahi[mt][1], ahi[mt][2], ahi[mt][3], aa);
            uint32_t al = a_addr(xlo, mw * 32 + mt * 16, kb, lane);
            ldsm_x4(alo[mt][0], alo[mt][1], alo[mt][2], alo[mt][3], al);
        }
#pragma unroll
        for (int p = 0; p < 2; p++) {
            uint32_t ba = b_addr(whi, nw * 32 + p * 16, kb, lane);
            ldsm_x4(bhi[2*p][0], bhi[2*p][1], bhi[2*p+1][0], bhi[2*p+1][1], ba);
            uint32_t bb = b_addr(wlo, nw * 32 + p * 16, kb, lane);
            ldsm_x4(blo[2*p][0], blo[2*p][1], blo[2*p+1][0], blo[2*p+1][1], bb);
        }
#pragma unroll
        for (int mt = 0; mt < 2; mt++)
#pragma unroll
            for (int nt = 0; nt < 4; nt++) {
                mma_bf16(acc[mt][nt], ahi[mt], bhi[nt][0], bhi[nt][1]);
                mma_bf16(acc[mt][nt], ahi[mt], blo[nt][0], blo[nt][1]);
                mma_bf16(acc[mt][nt], alo[mt], bhi[nt][0], bhi[nt][1]);
            }
    }
    __syncthreads();

    float* stage = (float*)smem;
    {
        const int rsub = lane >> 2;
        const int csub = (lane & 3) * 2;
#pragma unroll
        for (int mt = 0; mt < 2; mt++)
#pragma unroll
            for (int nt = 0; nt < 4; nt++) {
                int row = mw * 32 + mt * 16 + rsub;
                int col = nw * 32 + nt * 8 + csub;
                *(float2*)(stage + row * STAGE_STRIDE + col) =
                    make_float2(acc[mt][nt][0], acc[mt][nt][1]);
                *(float2*)(stage + (row + 8) * STAGE_STRIDE + col) =
                    make_float2(acc[mt][nt][2], acc[mt][nt][3]);
            }
    }
    __syncthreads();

    {
        const int r  = tid >> 2;
        const int qh = tid & 3;
        float* row = stage + r * STAGE_STRIDE + qh * 32;
        float s = 0.f, q = 0.f;
#pragma unroll
        for (int i = 0; i < 8; i++) {
            float4 v = ((float4*)row)[i];
            const int c = qh * 32 + i * 4;
            v.x = fmaxf(v.x + sB[c + 0], 0.f);
            v.y = fmaxf(v.y + sB[c + 1], 0.f);
            v.z = fmaxf(v.z + sB[c + 2], 0.f);
            v.w = fmaxf(v.w + sB[c + 3], 0.f);
            ((float4*)row)[i] = v;
            s += v.x + v.y + v.z + v.w;
            q = fmaf(v.x, v.x, q); q = fmaf(v.y, v.y, q);
            q = fmaf(v.z, v.z, q); q = fmaf(v.w, v.w, q);
        }
        s += __shfl_xor_sync(0xffffffffu, s, 1);
        q += __shfl_xor_sync(0xffffffffu, q, 1);
        s += __shfl_xor_sync(0xffffffffu, s, 2);
        q += __shfl_xor_sync(0xffffffffu, q, 2);
        float mean = s * (1.f / DIM);
        float var  = q * (1.f / DIM) - mean * mean + 1e-9f;
        float rs   = rsqrtf(var);

        const int g = gbase + r;
        if (g < N_NODES) {
            float4* op = (float4*)(out + (size_t)g * DIM + qh * 32);
#pragma unroll
            for (int i = 0; i < 8; i++) {
                float4 v = ((float4*)row)[i];
                const int c = qh * 32 + i * 4;
                float4 rv;
                rv.x = (v.x - mean) * rs * sS[c + 0] + sO[c + 0];
                rv.y = (v.y - mean) * rs * sS[c + 1] + sO[c + 1];
                rv.z = (v.z - mean) * rs * sS[c + 2] + sO[c + 2];
                rv.w = (v.w - mean) * rs * sS[c + 3] + sO[c + 3];
                if (MODE == 1) {
                    float4 p = op[i];
                    rv.x += p.x; rv.y += p.y; rv.z += p.z; rv.w += p.w;
                }
                op[i] = rv;
            }
        }
    }
}

// ---------------------------------------------------------------------------
struct ForkResources {
    cudaStream_t s2  = nullptr;
    cudaEvent_t  ev1 = nullptr, ev2 = nullptr;
    bool ok = false;
    ForkResources() {
        if (cudaStreamCreateWithFlags(&s2, cudaStreamNonBlocking) != cudaSuccess) return;
        if (cudaEventCreateWithFlags(&ev1, cudaEventDisableTiming) != cudaSuccess) return;
        if (cudaEventCreateWithFlags(&ev2, cudaEventDisableTiming) != cudaSuccess) return;
        ok = true;
    }
};
static ForkResources g_fork;

// ---------------------------------------------------------------------------
// stream0: count -> scan_offsets -> fill -> gather --------\
// s2:      wconv -> mma_self --------------------------------join-> mma_neigh
// ---------------------------------------------------------------------------
extern "C" void kernel_launch(void* const* d_in, const int* in_sizes, int n_in,
                              void* d_out, int out_size) {
    const float* feat_in  = (const float*)d_in[0];
    const int*   edge_row = (const int*)  d_in[1];
    const int*   edge_col = (const int*)  d_in[2];
    const float* edge_val = (const float*)d_in[3];
    const float* W_self   = (const float*)d_in[4];
    const float* b_self   = (const float*)d_in[5];
    const float* W_neigh  = (const float*)d_in[6];
    const float* b_neigh  = (const float*)d_in[7];
    const float* scale    = (const float*)d_in[8];
    const float* offset   = (const float*)d_in[9];
    float* out = (float*)d_out;

    int *cnt, *ofs, *cur;
    int2 *pack;
    void *wshi, *wslo, *wnhi, *wnlo, *xhi, *xlo;
    cudaGetSymbolAddress((void**)&cnt,   g_cnt);
    cudaGetSymbolAddress((void**)&ofs,   g_ofs);
    cudaGetSymbolAddress((void**)&cur,   g_cur);
    cudaGetSymbolAddress((void**)&pack,  g_pack);
    cudaGetSymbolAddress(&wshi, g_wshi);
    cudaGetSymbolAddress(&wslo, g_wslo);
    cudaGetSymbolAddress(&wnhi, g_wnhi);
    cudaGetSymbolAddress(&wnlo, g_wnlo);
    cudaGetSymbolAddress(&xhi,  g_xhi);
    cudaGetSymbolAddress(&xlo,  g_xlo);

    cudaFuncSetAttribute(mma_branch<0>,
                         cudaFuncAttributeMaxDynamicSharedMemorySize, GEMM_SMEM);
    cudaFuncSetAttribute(mma_branch<1>,
                         cudaFuncAttributeMaxDynamicSharedMemorySize, GEMM_SMEM);

    const int eb  = (N_EDGES + 255) / 256;
    const int eb4 = (N_EDGES / 4 + 255) / 256;
    const int gb  = (N_TILES * TILE_M * 32 + 255) / 256;   // warp per node (incl. tail)

    if (g_fork.ok) {
        cudaEventRecord(g_fork.ev1, 0);
        cudaStreamWaitEvent(g_fork.s2, g_fork.ev1, 0);

        wconv_kernel<<<16, 256, 0, g_fork.s2>>>(W_self, W_neigh);
        mma_branch<0><<<N_TILES, 256, GEMM_SMEM, g_fork.s2>>>(
            feat_in, (const uint4*)wshi, (const uint4*)wslo, nullptr, nullptr,
            b_self, scale, offset, 0, out);

        count_kernel<<<eb4, 256>>>((const int4*)edge_row, cnt);
        scan_offsets_kernel<<<NB_SCAN, SCAN_BS>>>(cnt, ofs, cur);
        fill_kernel<<<eb, 256>>>(edge_row, edge_col, edge_val, cur, pack);
        gather_kernel<<<gb, 256>>>((const float4*)feat_in, ofs, pack);

        cudaEventRecord(g_fork.ev2, g_fork.s2);
        cudaStreamWaitEvent(0, g_fork.ev2, 0);

        mma_branch<1><<<N_TILES, 256, GEMM_SMEM>>>(
            nullptr, (const uint4*)wnhi, (const uint4*)wnlo,
            (const uint4*)xhi, (const uint4*)xlo,
            b_neigh, scale, offset, DIM, out);
    } else {
        wconv_kernel<<<16, 256>>>(W_self, W_neigh);
        count_kernel<<<eb4, 256>>>((const int4*)edge_row, cnt);
        scan_offsets_kernel<<<NB_SCAN, SCAN_BS>>>(cnt, ofs, cur);
        fill_kernel<<<eb, 256>>>(edge_row, edge_col, edge_val, cur, pack);
        mma_branch<0><<<N_TILES, 256, GEMM_SMEM>>>(
            feat_in, (const uint4*)wshi, (const uint4*)wslo, nullptr, nullptr,
            b_self, scale, offset, 0, out);
        gather_kernel<<<gb, 256>>>((const float4*)feat_in, ofs, pack);
        mma_branch<1><<<N_TILES, 256, GEMM_SMEM>>>(
            nullptr, (const uint4*)wnhi, (const uint4*)wnlo,
            (const uint4*)xhi, (const uint4*)xlo,
            b_neigh, scale, offset, DIM, out);
    }
}

// round 15
// speedup vs baseline: 1.0295x; 1.0295x over previous
#include <cuda_runtime.h>
#include <cuda_bf16.h>
#include <cstdint>

#define N_NODES 50000
#define N_EDGES 800000
#define DIM     128

#define TILE_M   64
#define N_TILES  ((N_NODES + TILE_M - 1) / TILE_M)   // 782

// ---------------- SMEM layout (bytes, dynamic) ----------------------------
#define OFF_XHI   0
#define OFF_XLO   16384
#define OFF_WHI   32768
#define OFF_WLO   65536
#define OFF_CONST 98304                  // bias/scale/offset: 3 x 512B
#define GEMM_SMEM (98304 + 1536)
#define STAGE_STRIDE 132                 // fp32 stage [64][132] overlays X tiles

// ---------------- scan partition ------------------------------------------
#define SCAN_BS   256
#define NB_SCAN   ((N_NODES + SCAN_BS - 1) / SCAN_BS)   // 196

// ---------------- scratch (__device__ globals; zero-initialized) ----------
__device__ int   g_cnt[N_NODES];                      // self-cleaned in offsets
__device__ int   g_ofs[N_NODES + 1];
__device__ int   g_cur[N_NODES];
__device__ int2  g_pack[N_EDGES];                     // (col, val bits)
__device__ int   g_bsum[NB_SCAN];
__device__ int   g_bbase[NB_SCAN];
// pre-swizzled bf16 tiles
__device__ __align__(16) char g_wshi[32768];
__device__ __align__(16) char g_wslo[32768];
__device__ __align__(16) char g_wnhi[32768];
__device__ __align__(16) char g_wnlo[32768];
__device__ __align__(16) char g_xhi[(size_t)N_TILES * 16384];   // 12.8MB
__device__ __align__(16) char g_xlo[(size_t)N_TILES * 16384];

// ---------------------------------------------------------------------------
// count: int4 edge loads, 4 REDs per thread (MLP=4). N_EDGES % 4 == 0.
// ---------------------------------------------------------------------------
__global__ void count_kernel(const int4* __restrict__ erow4, int* __restrict__ cnt) {
    int e = blockIdx.x * blockDim.x + threadIdx.x;
    if (e < N_EDGES / 4) {
        int4 r = erow4[e];
        atomicAdd(&cnt[r.x], 1);
        atomicAdd(&cnt[r.y], 1);
        atomicAdd(&cnt[r.z], 1);
        atomicAdd(&cnt[r.w], 1);
    }
}

// phase 1: per-block sum of SCAN_BS counts
__global__ void __launch_bounds__(SCAN_BS) bsum_kernel(const int* __restrict__ cnt,
                                                       int* __restrict__ bsum) {
    __shared__ int red[SCAN_BS / 32];
    int i = blockIdx.x * SCAN_BS + threadIdx.x;
    int v = (i < N_NODES) ? cnt[i] : 0;
#pragma unroll
    for (int o = 16; o; o >>= 1) v += __shfl_xor_sync(0xffffffffu, v, o);
    if ((threadIdx.x & 31) == 0) red[threadIdx.x >> 5] = v;
    __syncthreads();
    if (threadIdx.x == 0) {
        int s = 0;
#pragma unroll
        for (int w = 0; w < SCAN_BS / 32; w++) s += red[w];
        bsum[blockIdx.x] = s;
    }
}

// phase 2: one block exclusive-scans the NB_SCAN block sums
__global__ void __launch_bounds__(256) scan_bsums(const int* __restrict__ bsum,
                                                  int* __restrict__ bbase) {
    __shared__ int sh[256];
    int t = threadIdx.x;
    sh[t] = (t < NB_SCAN) ? bsum[t] : 0;
    __syncthreads();
#pragma unroll
    for (int o = 1; o < 256; o <<= 1) {
        int v = (t >= o) ? sh[t - o] : 0;
        __syncthreads();
        sh[t] += v;
        __syncthreads();
    }
    if (t < NB_SCAN) bbase[t] = (t == 0) ? 0 : sh[t - 1];
}

// phase 3: per-block exclusive scan + base -> ofs, cur; self-cleans cnt
__global__ void __launch_bounds__(SCAN_BS) offsets_kernel(
    int* __restrict__ cnt, const int* __restrict__ bbase,
    int* __restrict__ ofs, int* __restrict__ cur)
{
    __shared__ int sh[SCAN_BS];
    int t = threadIdx.x;
    int i = blockIdx.x * SCAN_BS + t;
    int v = (i < N_NODES) ? cnt[i] : 0;
    if (i < N_NODES) cnt[i] = 0;          // self-clean for next replay
    sh[t] = v;
    __syncthreads();
#pragma unroll
    for (int o = 1; o < SCAN_BS; o <<= 1) {
        int u = (t >= o) ? sh[t - o] : 0;
        __syncthreads();
        sh[t] += u;
        __syncthreads();
    }
    if (i < N_NODES) {
        int excl = bbase[blockIdx.x] + sh[t] - v;
        ofs[i] = excl;
        cur[i] = excl;
    }
    if (i == N_NODES - 1) ofs[N_NODES] = N_EDGES;
}

// fill: 4 edges per thread (int4/float4 loads, 4 independent atomic+store chains)
__global__ void fill_kernel(const int4* __restrict__ erow4, const int4* __restrict__ ecol4,
                            const float4* __restrict__ eval4,
                            int* __restrict__ cur, int2* __restrict__ pack) {
    int e = blockIdx.x * blockDim.x + threadIdx.x;
    if (e >= N_EDGES / 4) return;
    int4   r = erow4[e];
    int4   c = ecol4[e];
    float4 v = eval4[e];
    int p0 = atomicAdd(&cur[r.x], 1);
    int p1 = atomicAdd(&cur[r.y], 1);
    int p2 = atomicAdd(&cur[r.z], 1);
    int p3 = atomicAdd(&cur[r.w], 1);
    pack[p0] = make_int2(c.x, __float_as_int(v.x));
    pack[p1] = make_int2(c.y, __float_as_int(v.y));
    pack[p2] = make_int2(c.z, __float_as_int(v.z));
    pack[p3] = make_int2(c.w, __float_as_int(v.w));
}

// ---------------------------------------------------------------------------
__device__ __forceinline__ uint32_t bt_off(int r, int k0) {
    return (uint32_t)(r * 256 + ((((k0 >> 3) ^ (r & 7)) & 15) << 4));
}
__device__ __forceinline__ void split_store8(const float* src, char* hi_base, char* lo_base,
                                             int r, int k0) {
    float4 a = ((const float4*)src)[0];
    float4 b = ((const float4*)src)[1];
    float v[8] = {a.x, a.y, a.z, a.w, b.x, b.y, b.z, b.w};
    uint32_t hp[4], lp[4];
#pragma unroll
    for (int e = 0; e < 4; e++) {
        __nv_bfloat16 h0 = __float2bfloat16(v[2 * e]);
        __nv_bfloat16 h1 = __float2bfloat16(v[2 * e + 1]);
        __nv_bfloat16 l0 = __float2bfloat16(v[2 * e]     - __bfloat162float(h0));
        __nv_bfloat16 l1 = __float2bfloat16(v[2 * e + 1] - __bfloat162float(h1));
        __nv_bfloat162 hh = __halves2bfloat162(h0, h1);
        __nv_bfloat162 ll = __halves2bfloat162(l0, l1);
        hp[e] = *(uint32_t*)&hh;
        lp[e] = *(uint32_t*)&ll;
    }
    uint32_t o = bt_off(r, k0);
    *(uint4*)(hi_base + o) = make_uint4(hp[0], hp[1], hp[2], hp[3]);
    *(uint4*)(lo_base + o) = make_uint4(lp[0], lp[1], lp[2], lp[3]);
}

// one-shot W conversion -> pre-swizzled bf16 hi/lo global tiles
__global__ void __launch_bounds__(256) wconv_kernel(const float* __restrict__ Ws,
                                                    const float* __restrict__ Wn) {
    int i = blockIdx.x * blockDim.x + threadIdx.x;   // 0..4095
    if (i >= 4096) return;
    int sel = i >> 11;
    int j   = i & 2047;
    int r = j >> 4, k0 = (j & 15) << 3;
    const float* W = sel ? Wn : Ws;
    char* hi = sel ? g_wnhi : g_wshi;
    char* lo = sel ? g_wnlo : g_wslo;
    split_store8(W + r * DIM + k0, hi, lo, r, k0);
}

// ---------------------------------------------------------------------------
// gather: WARP per node, lane = float4 of 4 dims, unroll x8; writes bf16 hi/lo
// directly in the per-tile swizzled layout the neigh GEMM consumes.
// ---------------------------------------------------------------------------
__global__ void __launch_bounds__(256, 4) gather_kernel(
    const float4* __restrict__ feat4, const int* __restrict__ ofs,
    const int2* __restrict__ pack)
{
    const int node = (blockIdx.x * blockDim.x + threadIdx.x) >> 5;
    const int lane = threadIdx.x & 31;
    if (node >= N_TILES * TILE_M) return;

    float4 acc = make_float4(0.f, 0.f, 0.f, 0.f);
    if (node < N_NODES) {
        const int beg = ofs[node];
        const int end = ofs[node + 1];
        int e = beg;
        for (; e + 8 <= end; e += 8) {
            int2 p[8];
            float4 x[8];
#pragma unroll
            for (int i = 0; i < 8; i++) p[i] = pack[e + i];
#pragma unroll
            for (int i = 0; i < 8; i++) x[i] = feat4[(size_t)p[i].x * 32 + lane];
#pragma unroll
            for (int i = 0; i < 8; i++) {
                float v = __int_as_float(p[i].y);
                acc.x = fmaf(v, x[i].x, acc.x); acc.y = fmaf(v, x[i].y, acc.y);
                acc.z = fmaf(v, x[i].z, acc.z); acc.w = fmaf(v, x[i].w, acc.w);
            }
        }
        for (; e + 4 <= end; e += 4) {
            int2 p[4];
            float4 x[4];
#pragma unroll
            for (int i = 0; i < 4; i++) p[i] = pack[e + i];
#pragma unroll
            for (int i = 0; i < 4; i++) x[i] = feat4[(size_t)p[i].x * 32 + lane];
#pragma unroll
            for (int i = 0; i < 4; i++) {
                float v = __int_as_float(p[i].y);
                acc.x = fmaf(v, x[i].x, acc.x); acc.y = fmaf(v, x[i].y, acc.y);
                acc.z = fmaf(v, x[i].z, acc.z); acc.w = fmaf(v, x[i].w, acc.w);
            }
        }
        for (; e < end; e++) {
            int2 p = pack[e];
            float v = __int_as_float(p.y);
            float4 x = feat4[(size_t)p.x * 32 + lane];
            acc.x = fmaf(v, x.x, acc.x); acc.y = fmaf(v, x.y, acc.y);
            acc.z = fmaf(v, x.z, acc.z); acc.w = fmaf(v, x.w, acc.w);
        }
    }

    __nv_bfloat16 h0 = __float2bfloat16(acc.x), h1 = __float2bfloat16(acc.y);
    __nv_bfloat16 h2 = __float2bfloat16(acc.z), h3 = __float2bfloat16(acc.w);
    __nv_bfloat16 l0 = __float2bfloat16(acc.x - __bfloat162float(h0));
    __nv_bfloat16 l1 = __float2bfloat16(acc.y - __bfloat162float(h1));
    __nv_bfloat16 l2 = __float2bfloat16(acc.z - __bfloat162float(h2));
    __nv_bfloat16 l3 = __float2bfloat16(acc.w - __bfloat162float(h3));
    __nv_bfloat162 hA = __halves2bfloat162(h0, h1), hB = __halves2bfloat162(h2, h3);
    __nv_bfloat162 lA = __halves2bfloat162(l0, l1), lB = __halves2bfloat162(l2, l3);

    const int tile = node >> 6, r = node & 63;
    const uint32_t off = (uint32_t)r * 256
                       + ((((lane >> 1) ^ (r & 7)) & 15) << 4) + ((lane & 1) << 3);
    char* hb = g_xhi + (size_t)tile * 16384;
    char* lb = g_xlo + (size_t)tile * 16384;
    *(uint2*)(hb + off) = make_uint2(*(uint32_t*)&hA, *(uint32_t*)&hB);
    *(uint2*)(lb + off) = make_uint2(*(uint32_t*)&lA, *(uint32_t*)&lB);
}

// ---------------------------------------------------------------------------
__device__ __forceinline__ uint32_t smem_u32(const void* p) {
    uint32_t a;
    asm("{ .reg .u64 t; cvta.to.shared.u64 t, %1; cvt.u32.u64 %0, t; }" : "=r"(a) : "l"(p));
    return a;
}
__device__ __forceinline__ void ldsm_x4(uint32_t& r0, uint32_t& r1,
                                        uint32_t& r2, uint32_t& r3, uint32_t a) {
    asm volatile("ldmatrix.sync.aligned.m8n8.x4.shared.b16 {%0,%1,%2,%3}, [%4];"
                 : "=r"(r0), "=r"(r1), "=r"(r2), "=r"(r3) : "r"(a));
}
__device__ __forceinline__ void mma_bf16(float* c, const uint32_t* a,
                                         uint32_t b0, uint32_t b1) {
    asm volatile("mma.sync.aligned.m16n8k16.row.col.f32.bf16.bf16.f32 "
                 "{%0,%1,%2,%3}, {%4,%5,%6,%7}, {%8,%9}, {%0,%1,%2,%3};"
                 : "+f"(c[0]), "+f"(c[1]), "+f"(c[2]), "+f"(c[3])
                 : "r"(a[0]), "r"(a[1]), "r"(a[2]), "r"(a[3]), "r"(b0), "r"(b1));
}
__device__ __forceinline__ uint32_t a_addr(uint32_t base, int m0, int kb, int lane) {
    int row = m0 + (lane & 15);
    int chunk = (kb >> 3) + (lane >> 4);
    return base + row * 256 + (((chunk ^ (row & 7)) & 15) << 4);
}
__device__ __forceinline__ uint32_t b_addr(uint32_t base, int n0, int kb, int lane) {
    int row = n0 + (lane & 7) + ((lane >> 4) << 3);
    int chunk = (kb >> 3) + ((lane >> 3) & 1);
    return base + row * 256 + (((chunk ^ (row & 7)) & 15) << 4);
}

// ---------------------------------------------------------------------------
// Tensor branch (mma.sync bf16 3-term split), TILE_M=64, 2 CTAs/SM.
// MODE 0 (self): X = feat_in (converted in-kernel), no accumulate.
// MODE 1 (neigh): X = pre-swizzled bf16 tiles from gather; accumulate.
// ---------------------------------------------------------------------------
template<int MODE>
__global__ void __launch_bounds__(256, 2) mma_branch(
    const float* __restrict__ X,
    const uint4* __restrict__ gwhi, const uint4* __restrict__ gwlo,
    const uint4* __restrict__ gxhi, const uint4* __restrict__ gxlo,
    const float* __restrict__ bias, const float* __restrict__ scale,
    const float* __restrict__ offset, int so, float* __restrict__ out)
{
    extern __shared__ char smem[];
    const uint32_t sb = smem_u32(smem);
    const int tid  = threadIdx.x;
    const int wid  = tid >> 5;
    const int lane = tid & 31;
    const int mw   = wid & 1;
    const int nw   = wid >> 1;
    const int gbase = blockIdx.x * TILE_M;

    for (int i = tid; i < 2048; i += 256) {
        ((uint4*)(smem + OFF_WHI))[i] = gwhi[i];
        ((uint4*)(smem + OFF_WLO))[i] = gwlo[i];
    }
    if (MODE == 0) {
        for (int i = tid; i < 1024; i += 256) {
            int r = i >> 4, k0 = (i & 15) << 3;
            int gr = gbase + r; if (gr >= N_NODES) gr = N_NODES - 1;
            split_store8(X + (size_t)gr * DIM + k0, smem + OFF_XHI, smem + OFF_XLO, r, k0);
        }
    } else {
        const uint4* xh = gxhi + (size_t)blockIdx.x * 1024;
        const uint4* xl = gxlo + (size_t)blockIdx.x * 1024;
        for (int i = tid; i < 1024; i += 256) {
            ((uint4*)(smem + OFF_XHI))[i] = xh[i];
            ((uint4*)(smem + OFF_XLO))[i] = xl[i];
        }
    }
    float* sB = (float*)(smem + OFF_CONST);
    float* sS = sB + 128;
    float* sO = sS + 128;
    if (tid < 32)       ((float4*)sB)[tid]      = ((const float4*)bias)[tid];
    else if (tid < 64)  ((float4*)sS)[tid - 32] = ((const float4*)(scale  + so))[tid - 32];
    else if (tid < 96)  ((float4*)sO)[tid - 64] = ((const float4*)(offset + so))[tid - 64];
    __syncthreads();

    float acc[2][4][4];
#pragma unroll
    for (int mt = 0; mt < 2; mt++)
#pragma unroll
        for (int nt = 0; nt < 4; nt++)
#pragma unroll
            for (int e = 0; e < 4; e++) acc[mt][nt][e] = 0.f;

    const uint32_t xhi = sb + OFF_XHI, xlo = sb + OFF_XLO;
    const uint32_t whi = sb + OFF_WHI, wlo = sb + OFF_WLO;

#pragma unroll
    for (int kb8 = 0; kb8 < 8; kb8++) {
        const int kb = kb8 * 16;
        uint32_t ahi[2][4], alo[2][4], bhi[4][2], blo[4][2];
#pragma unroll
        for (int mt = 0; mt < 2; mt++) {
            uint32_t aa = a_addr(xhi, mw * 32 + mt * 16, kb, lane);
            ldsm_x4(ahi[mt][0], ahi[mt][1], ahi[mt][2], ahi[mt][3], aa);
            uint32_t al = a_addr(xlo, mw * 32 + mt * 16, kb, lane);
            ldsm_x4(alo[mt][0], alo[mt][1], alo[mt][2], alo[mt][3], al);
        }
#pragma unroll
        for (int p = 0; p < 2; p++) {
            uint32_t ba = b_addr(whi, nw * 32 + p * 16, kb, lane);
            ldsm_x4(bhi[2*p][0], bhi[2*p][1], bhi[2*p+1][0], bhi[2*p+1][1], ba);
            uint32_t bb = b_addr(wlo, nw * 32 + p * 16, kb, lane);
            ldsm_x4(blo[2*p][0], blo[2*p][1], blo[2*p+1][0], blo[2*p+1][1], bb);
        }
#pragma unroll
        for (int mt = 0; mt < 2; mt++)
#pragma unroll
            for (int nt = 0; nt < 4; nt++) {
                mma_bf16(acc[mt][nt], ahi[mt], bhi[nt][0], bhi[nt][1]);
                mma_bf16(acc[mt][nt], ahi[mt], blo[nt][0], blo[nt][1]);
                mma_bf16(acc[mt][nt], alo[mt], bhi[nt][0], bhi[nt][1]);
            }
    }
    __syncthreads();

    float* stage = (float*)smem;
    {
        const int rsub = lane >> 2;
        const int csub = (lane & 3) * 2;
#pragma unroll
        for (int mt = 0; mt < 2; mt++)
#pragma unroll
            for (int nt = 0; nt < 4; nt++) {
                int row = mw * 32 + mt * 16 + rsub;
                int col = nw * 32 + nt * 8 + csub;
                *(float2*)(stage + row * STAGE_STRIDE + col) =
                    make_float2(acc[mt][nt][0], acc[mt][nt][1]);
                *(float2*)(stage + (row + 8) * STAGE_STRIDE + col) =
                    make_float2(acc[mt][nt][2], acc[mt][nt][3]);
            }
    }
    __syncthreads();

    {
        const int r  = tid >> 2;
        const int qh = tid & 3;
        float* row = stage + r * STAGE_STRIDE + qh * 32;
        float s = 0.f, q = 0.f;
#pragma unroll
        for (int i = 0; i < 8; i++) {
            float4 v = ((float4*)row)[i];
            const int c = qh * 32 + i * 4;
            v.x = fmaxf(v.x + sB[c + 0], 0.f);
            v.y = fmaxf(v.y + sB[c + 1], 0.f);
            v.z = fmaxf(v.z + sB[c + 2], 0.f);
            v.w = fmaxf(v.w + sB[c + 3], 0.f);
            ((float4*)row)[i] = v;
            s += v.x + v.y + v.z + v.w;
            q = fmaf(v.x, v.x, q); q = fmaf(v.y, v.y, q);
            q = fmaf(v.z, v.z, q); q = fmaf(v.w, v.w, q);
        }
        s += __shfl_xor_sync(0xffffffffu, s, 1);
        q += __shfl_xor_sync(0xffffffffu, q, 1);
        s += __shfl_xor_sync(0xffffffffu, s, 2);
        q += __shfl_xor_sync(0xffffffffu, q, 2);
        float mean = s * (1.f / DIM);
        float var  = q * (1.f / DIM) - mean * mean + 1e-9f;
        float rs   = rsqrtf(var);

        const int g = gbase + r;
        if (g < N_NODES) {
            float4* op = (float4*)(out + (size_t)g * DIM + qh * 32);
#pragma unroll
            for (int i = 0; i < 8; i++) {
                float4 v = ((float4*)row)[i];
                const int c = qh * 32 + i * 4;
                float4 rv;
                rv.x = (v.x - mean) * rs * sS[c + 0] + sO[c + 0];
                rv.y = (v.y - mean) * rs * sS[c + 1] + sO[c + 1];
                rv.z = (v.z - mean) * rs * sS[c + 2] + sO[c + 2];
                rv.w = (v.w - mean) * rs * sS[c + 3] + sO[c + 3];
                if (MODE == 1) {
                    float4 p = op[i];
                    rv.x += p.x; rv.y += p.y; rv.z += p.z; rv.w += p.w;
                }
                op[i] = rv;
            }
        }
    }
}

// ---------------------------------------------------------------------------
struct ForkResources {
    cudaStream_t s2  = nullptr;
    cudaEvent_t  ev1 = nullptr, ev2 = nullptr;
    bool ok = false;
    ForkResources() {
        if (cudaStreamCreateWithFlags(&s2, cudaStreamNonBlocking) != cudaSuccess) return;
        if (cudaEventCreateWithFlags(&ev1, cudaEventDisableTiming) != cudaSuccess) return;
        if (cudaEventCreateWithFlags(&ev2, cudaEventDisableTiming) != cudaSuccess) return;
        ok = true;
    }
};
static ForkResources g_fork;

// ---------------------------------------------------------------------------
// stream0: count -> bsum -> scan_bsums -> offsets -> fill -> gather --\
// s2:      wconv -> mma_self --------------------------------------------join-> mma_neigh
// ---------------------------------------------------------------------------
extern "C" void kernel_launch(void* const* d_in, const int* in_sizes, int n_in,
                              void* d_out, int out_size) {
    const float* feat_in  = (const float*)d_in[0];
    const int*   edge_row = (const int*)  d_in[1];
    const int*   edge_col = (const int*)  d_in[2];
    const float* edge_val = (const float*)d_in[3];
    const float* W_self   = (const float*)d_in[4];
    const float* b_self   = (const float*)d_in[5];
    const float* W_neigh  = (const float*)d_in[6];
    const float* b_neigh  = (const float*)d_in[7];
    const float* scale    = (const float*)d_in[8];
    const float* offset   = (const float*)d_in[9];
    float* out = (float*)d_out;

    int *cnt, *ofs, *cur, *bsum, *bbase;
    int2 *pack;
    void *wshi, *wslo, *wnhi, *wnlo, *xhi, *xlo;
    cudaGetSymbolAddress((void**)&cnt,   g_cnt);
    cudaGetSymbolAddress((void**)&ofs,   g_ofs);
    cudaGetSymbolAddress((void**)&cur,   g_cur);
    cudaGetSymbolAddress((void**)&pack,  g_pack);
    cudaGetSymbolAddress((void**)&bsum,  g_bsum);
    cudaGetSymbolAddress((void**)&bbase, g_bbase);
    cudaGetSymbolAddress(&wshi, g_wshi);
    cudaGetSymbolAddress(&wslo, g_wslo);
    cudaGetSymbolAddress(&wnhi, g_wnhi);
    cudaGetSymbolAddress(&wnlo, g_wnlo);
    cudaGetSymbolAddress(&xhi,  g_xhi);
    cudaGetSymbolAddress(&xlo,  g_xlo);

    cudaFuncSetAttribute(mma_branch<0>,
                         cudaFuncAttributeMaxDynamicSharedMemorySize, GEMM_SMEM);
    cudaFuncSetAttribute(mma_branch<1>,
                         cudaFuncAttributeMaxDynamicSharedMemorySize, GEMM_SMEM);

    const int eb4 = (N_EDGES / 4 + 255) / 256;
    const int gb  = (N_TILES * TILE_M * 32 + 255) / 256;   // warp per node (incl. tail)

    if (g_fork.ok) {
        cudaEventRecord(g_fork.ev1, 0);
        cudaStreamWaitEvent(g_fork.s2, g_fork.ev1, 0);

        wconv_kernel<<<16, 256, 0, g_fork.s2>>>(W_self, W_neigh);
        mma_branch<0><<<N_TILES, 256, GEMM_SMEM, g_fork.s2>>>(
            feat_in, (const uint4*)wshi, (const uint4*)wslo, nullptr, nullptr,
            b_self, scale, offset, 0, out);

        count_kernel<<<eb4, 256>>>((const int4*)edge_row, cnt);
        bsum_kernel<<<NB_SCAN, SCAN_BS>>>(cnt, bsum);
        scan_bsums<<<1, 256>>>(bsum, bbase);
        offsets_kernel<<<NB_SCAN, SCAN_BS>>>(cnt, bbase, ofs, cur);
        fill_kernel<<<eb4, 256>>>((const int4*)edge_row, (const int4*)edge_col,
                                  (const float4*)edge_val, cur, pack);
        gather_kernel<<<gb, 256>>>((const float4*)feat_in, ofs, pack);

        cudaEventRecord(g_fork.ev2, g_fork.s2);
        cudaStreamWaitEvent(0, g_fork.ev2, 0);

        mma_branch<1><<<N_TILES, 256, GEMM_SMEM>>>(
            nullptr, (const uint4*)wnhi, (const uint4*)wnlo,
            (const uint4*)xhi, (const uint4*)xlo,
            b_neigh, scale, offset, DIM, out);
    } else {
        wconv_kernel<<<16, 256>>>(W_self, W_neigh);
        count_kernel<<<eb4, 256>>>((const int4*)edge_row, cnt);
        bsum_kernel<<<NB_SCAN, SCAN_BS>>>(cnt, bsum);
        scan_bsums<<<1, 256>>>(bsum, bbase);
        offsets_kernel<<<NB_SCAN, SCAN_BS>>>(cnt, bbase, ofs, cur);
        fill_kernel<<<eb4, 256>>>((const int4*)edge_row, (const int4*)edge_col,
                                  (const float4*)edge_val, cur, pack);
        mma_branch<0><<<N_TILES, 256, GEMM_SMEM>>>(
            feat_in, (const uint4*)wshi, (const uint4*)wslo, nullptr, nullptr,
            b_self, scale, offset, 0, out);
        gather_kernel<<<gb, 256>>>((const float4*)feat_in, ofs, pack);
        mma_branch<1><<<N_TILES, 256, GEMM_SMEM>>>(
            nullptr, (const uint4*)wnhi, (const uint4*)wnlo,
            (const uint4*)xhi, (const uint4*)xlo,
            b_neigh, scale, offset, DIM, out);
    }
}

// round 16
// speedup vs baseline: 1.1231x; 1.0910x over previous
#include <cuda_runtime.h>
#include <cuda_bf16.h>
#include <cstdint>

#define N_NODES 50000
#define N_EDGES 800000
#define DIM     128

#define TILE_M   64
#define N_TILES  ((N_NODES + TILE_M - 1) / TILE_M)   // 782

// ---------------- merged-kernel SMEM layout (bytes) ------------------------
// Phase region (reused A->B): X at 0 (hi 16K + lo 16K), W at 32K (hi 32K + lo 32K)
#define OFF_X     0
#define OFF_W     32768
#define OFF_CONST 98304        // b_self 512 | b_neigh 512 | scale 1024 | offset 1024
#define MERGED_SMEM (98304 + 3072)
// epilogue stages overlay the phase region
#define STAGE_STRIDE 132
#define OFF_STAGE_A 0
#define OFF_STAGE_B 34816      // 64*132*4 = 33792, padded

// ---------------- scan partition ------------------------------------------
#define SCAN_BS   256
#define NB_SCAN   ((N_NODES + SCAN_BS - 1) / SCAN_BS)   // 196

// ---------------- scratch (__device__ globals; zero-initialized) ----------
__device__ int   g_cnt[N_NODES];                      // self-cleaned in offsets
__device__ int   g_ofs[N_NODES + 1];
__device__ int   g_cur[N_NODES];
__device__ int2  g_pack[N_EDGES];                     // (col, val bits)
__device__ int   g_bsum[NB_SCAN];
__device__ int   g_bbase[NB_SCAN];
__device__ __align__(16) char g_wshi[32768];
__device__ __align__(16) char g_wslo[32768];
__device__ __align__(16) char g_wnhi[32768];
__device__ __align__(16) char g_wnlo[32768];
__device__ __align__(16) char g_xhi[(size_t)N_TILES * 16384];   // 12.8MB
__device__ __align__(16) char g_xlo[(size_t)N_TILES * 16384];

// ---------------------------------------------------------------------------
__global__ void count_kernel(const int4* __restrict__ erow4, int* __restrict__ cnt) {
    int e = blockIdx.x * blockDim.x + threadIdx.x;
    if (e < N_EDGES / 4) {
        int4 r = erow4[e];
        atomicAdd(&cnt[r.x], 1);
        atomicAdd(&cnt[r.y], 1);
        atomicAdd(&cnt[r.z], 1);
        atomicAdd(&cnt[r.w], 1);
    }
}

__global__ void __launch_bounds__(SCAN_BS) bsum_kernel(const int* __restrict__ cnt,
                                                       int* __restrict__ bsum) {
    __shared__ int red[SCAN_BS / 32];
    int i = blockIdx.x * SCAN_BS + threadIdx.x;
    int v = (i < N_NODES) ? cnt[i] : 0;
#pragma unroll
    for (int o = 16; o; o >>= 1) v += __shfl_xor_sync(0xffffffffu, v, o);
    if ((threadIdx.x & 31) == 0) red[threadIdx.x >> 5] = v;
    __syncthreads();
    if (threadIdx.x == 0) {
        int s = 0;
#pragma unroll
        for (int w = 0; w < SCAN_BS / 32; w++) s += red[w];
        bsum[blockIdx.x] = s;
    }
}

__global__ void __launch_bounds__(256) scan_bsums(const int* __restrict__ bsum,
                                                  int* __restrict__ bbase) {
    __shared__ int sh[256];
    int t = threadIdx.x;
    sh[t] = (t < NB_SCAN) ? bsum[t] : 0;
    __syncthreads();
#pragma unroll
    for (int o = 1; o < 256; o <<= 1) {
        int v = (t >= o) ? sh[t - o] : 0;
        __syncthreads();
        sh[t] += v;
        __syncthreads();
    }
    if (t < NB_SCAN) bbase[t] = (t == 0) ? 0 : sh[t - 1];
}

__global__ void __launch_bounds__(SCAN_BS) offsets_kernel(
    int* __restrict__ cnt, const int* __restrict__ bbase,
    int* __restrict__ ofs, int* __restrict__ cur)
{
    __shared__ int sh[SCAN_BS];
    int t = threadIdx.x;
    int i = blockIdx.x * SCAN_BS + t;
    int v = (i < N_NODES) ? cnt[i] : 0;
    if (i < N_NODES) cnt[i] = 0;          // self-clean for next replay
    sh[t] = v;
    __syncthreads();
#pragma unroll
    for (int o = 1; o < SCAN_BS; o <<= 1) {
        int u = (t >= o) ? sh[t - o] : 0;
        __syncthreads();
        sh[t] += u;
        __syncthreads();
    }
    if (i < N_NODES) {
        int excl = bbase[blockIdx.x] + sh[t] - v;
        ofs[i] = excl;
        cur[i] = excl;
    }
    if (i == N_NODES - 1) ofs[N_NODES] = N_EDGES;
}

__global__ void fill_kernel(const int4* __restrict__ erow4, const int4* __restrict__ ecol4,
                            const float4* __restrict__ eval4,
                            int* __restrict__ cur, int2* __restrict__ pack) {
    int e = blockIdx.x * blockDim.x + threadIdx.x;
    if (e >= N_EDGES / 4) return;
    int4   r = erow4[e];
    int4   c = ecol4[e];
    float4 v = eval4[e];
    int p0 = atomicAdd(&cur[r.x], 1);
    int p1 = atomicAdd(&cur[r.y], 1);
    int p2 = atomicAdd(&cur[r.z], 1);
    int p3 = atomicAdd(&cur[r.w], 1);
    pack[p0] = make_int2(c.x, __float_as_int(v.x));
    pack[p1] = make_int2(c.y, __float_as_int(v.y));
    pack[p2] = make_int2(c.z, __float_as_int(v.z));
    pack[p3] = make_int2(c.w, __float_as_int(v.w));
}

// ---------------------------------------------------------------------------
__device__ __forceinline__ uint32_t bt_off(int r, int k0) {
    return (uint32_t)(r * 256 + ((((k0 >> 3) ^ (r & 7)) & 15) << 4));
}
__device__ __forceinline__ void split_store8(const float* src, char* hi_base, char* lo_base,
                                             int r, int k0) {
    float4 a = ((const float4*)src)[0];
    float4 b = ((const float4*)src)[1];
    float v[8] = {a.x, a.y, a.z, a.w, b.x, b.y, b.z, b.w};
    uint32_t hp[4], lp[4];
#pragma unroll
    for (int e = 0; e < 4; e++) {
        __nv_bfloat16 h0 = __float2bfloat16(v[2 * e]);
        __nv_bfloat16 h1 = __float2bfloat16(v[2 * e + 1]);
        __nv_bfloat16 l0 = __float2bfloat16(v[2 * e]     - __bfloat162float(h0));
        __nv_bfloat16 l1 = __float2bfloat16(v[2 * e + 1] - __bfloat162float(h1));
        __nv_bfloat162 hh = __halves2bfloat162(h0, h1);
        __nv_bfloat162 ll = __halves2bfloat162(l0, l1);
        hp[e] = *(uint32_t*)&hh;
        lp[e] = *(uint32_t*)&ll;
    }
    uint32_t o = bt_off(r, k0);
    *(uint4*)(hi_base + o) = make_uint4(hp[0], hp[1], hp[2], hp[3]);
    *(uint4*)(lo_base + o) = make_uint4(lp[0], lp[1], lp[2], lp[3]);
}

// one-shot W conversion -> pre-swizzled bf16 hi/lo global tiles
__global__ void __launch_bounds__(256) wconv_kernel(const float* __restrict__ Ws,
                                                    const float* __restrict__ Wn) {
    int i = blockIdx.x * blockDim.x + threadIdx.x;   // 0..4095
    if (i >= 4096) return;
    int sel = i >> 11;
    int j   = i & 2047;
    int r = j >> 4, k0 = (j & 15) << 3;
    const float* W = sel ? Wn : Ws;
    char* hi = sel ? g_wnhi : g_wshi;
    char* lo = sel ? g_wnlo : g_wslo;
    split_store8(W + r * DIM + k0, hi, lo, r, k0);
}

// ---------------------------------------------------------------------------
// gather: WARP per node, lane = float4 of 4 dims, unroll x8; writes bf16 hi/lo
// directly in the per-tile swizzled layout the merged GEMM consumes.
// ---------------------------------------------------------------------------
__global__ void __launch_bounds__(256, 4) gather_kernel(
    const float4* __restrict__ feat4, const int* __restrict__ ofs,
    const int2* __restrict__ pack)
{
    const int node = (blockIdx.x * blockDim.x + threadIdx.x) >> 5;
    const int lane = threadIdx.x & 31;
    if (node >= N_TILES * TILE_M) return;

    float4 acc = make_float4(0.f, 0.f, 0.f, 0.f);
    if (node < N_NODES) {
        const int beg = ofs[node];
        const int end = ofs[node + 1];
        int e = beg;
        for (; e + 8 <= end; e += 8) {
            int2 p[8];
            float4 x[8];
#pragma unroll
            for (int i = 0; i < 8; i++) p[i] = pack[e + i];
#pragma unroll
            for (int i = 0; i < 8; i++) x[i] = feat4[(size_t)p[i].x * 32 + lane];
#pragma unroll
            for (int i = 0; i < 8; i++) {
                float v = __int_as_float(p[i].y);
                acc.x = fmaf(v, x[i].x, acc.x); acc.y = fmaf(v, x[i].y, acc.y);
                acc.z = fmaf(v, x[i].z, acc.z); acc.w = fmaf(v, x[i].w, acc.w);
            }
        }
        for (; e + 4 <= end; e += 4) {
            int2 p[4];
            float4 x[4];
#pragma unroll
            for (int i = 0; i < 4; i++) p[i] = pack[e + i];
#pragma unroll
            for (int i = 0; i < 4; i++) x[i] = feat4[(size_t)p[i].x * 32 + lane];
#pragma unroll
            for (int i = 0; i < 4; i++) {
                float v = __int_as_float(p[i].y);
                acc.x = fmaf(v, x[i].x, acc.x); acc.y = fmaf(v, x[i].y, acc.y);
                acc.z = fmaf(v, x[i].z, acc.z); acc.w = fmaf(v, x[i].w, acc.w);
            }
        }
        for (; e < end; e++) {
            int2 p = pack[e];
            float v = __int_as_float(p.y);
            float4 x = feat4[(size_t)p.x * 32 + lane];
            acc.x = fmaf(v, x.x, acc.x); acc.y = fmaf(v, x.y, acc.y);
            acc.z = fmaf(v, x.z, acc.z); acc.w = fmaf(v, x.w, acc.w);
        }
    }

    __nv_bfloat16 h0 = __float2bfloat16(acc.x), h1 = __float2bfloat16(acc.y);
    __nv_bfloat16 h2 = __float2bfloat16(acc.z), h3 = __float2bfloat16(acc.w);
    __nv_bfloat16 l0 = __float2bfloat16(acc.x - __bfloat162float(h0));
    __nv_bfloat16 l1 = __float2bfloat16(acc.y - __bfloat162float(h1));
    __nv_bfloat16 l2 = __float2bfloat16(acc.z - __bfloat162float(h2));
    __nv_bfloat16 l3 = __float2bfloat16(acc.w - __bfloat162float(h3));
    __nv_bfloat162 hA = __halves2bfloat162(h0, h1), hB = __halves2bfloat162(h2, h3);
    __nv_bfloat162 lA = __halves2bfloat162(l0, l1), lB = __halves2bfloat162(l2, l3);

    const int tile = node >> 6, r = node & 63;
    const uint32_t off = (uint32_t)r * 256
                       + ((((lane >> 1) ^ (r & 7)) & 15) << 4) + ((lane & 1) << 3);
    char* hb = g_xhi + (size_t)tile * 16384;
    char* lb = g_xlo + (size_t)tile * 16384;
    *(uint2*)(hb + off) = make_uint2(*(uint32_t*)&hA, *(uint32_t*)&hB);
    *(uint2*)(lb + off) = make_uint2(*(uint32_t*)&lA, *(uint32_t*)&lB);
}

// ---------------------------------------------------------------------------
__device__ __forceinline__ uint32_t smem_u32(const void* p) {
    uint32_t a;
    asm("{ .reg .u64 t; cvta.to.shared.u64 t, %1; cvt.u32.u64 %0, t; }" : "=r"(a) : "l"(p));
    return a;
}
__device__ __forceinline__ void ldsm_x4(uint32_t& r0, uint32_t& r1,
                                        uint32_t& r2, uint32_t& r3, uint32_t a) {
    asm volatile("ldmatrix.sync.aligned.m8n8.x4.shared.b16 {%0,%1,%2,%3}, [%4];"
                 : "=r"(r0), "=r"(r1), "=r"(r2), "=r"(r3) : "r"(a));
}
__device__ __forceinline__ void mma_bf16(float* c, const uint32_t* a,
                                         uint32_t b0, uint32_t b1) {
    asm volatile("mma.sync.aligned.m16n8k16.row.col.f32.bf16.bf16.f32 "
                 "{%0,%1,%2,%3}, {%4,%5,%6,%7}, {%8,%9}, {%0,%1,%2,%3};"
                 : "+f"(c[0]), "+f"(c[1]), "+f"(c[2]), "+f"(c[3])
                 : "r"(a[0]), "r"(a[1]), "r"(a[2]), "r"(a[3]), "r"(b0), "r"(b1));
}
__device__ __forceinline__ uint32_t a_addr(uint32_t base, int m0, int kb, int lane) {
    int row = m0 + (lane & 15);
    int chunk = (kb >> 3) + (lane >> 4);
    return base + row * 256 + (((chunk ^ (row & 7)) & 15) << 4);
}
__device__ __forceinline__ uint32_t b_addr(uint32_t base, int n0, int kb, int lane) {
    int row = n0 + (lane & 7) + ((lane >> 4) << 3);
    int chunk = (kb >> 3) + ((lane >> 3) & 1);
    return base + row * 256 + (((chunk ^ (row & 7)) & 15) << 4);
}

// shared mainloop: X at sb+OFF_X (hi/lo), W at sb+OFF_W (hi/lo) -> acc[2][4][4]
__device__ __forceinline__ void run_gemm(uint32_t sb, int mw, int nw, int lane,
                                         float acc[2][4][4]) {
    const uint32_t xhi = sb + OFF_X,  xlo = sb + OFF_X + 16384;
    const uint32_t whi = sb + OFF_W,  wlo = sb + OFF_W + 32768;
#pragma unroll
    for (int mt = 0; mt < 2; mt++)
#pragma unroll
        for (int nt = 0; nt < 4; nt++)
#pragma unroll
            for (int e = 0; e < 4; e++) acc[mt][nt][e] = 0.f;

#pragma unroll
    for (int kb8 = 0; kb8 < 8; kb8++) {
        const int kb = kb8 * 16;
        uint32_t ahi[2][4], alo[2][4], bhi[4][2], blo[4][2];
#pragma unroll
        for (int mt = 0; mt < 2; mt++) {
            uint32_t aa = a_addr(xhi, mw * 32 + mt * 16, kb, lane);
            ldsm_x4(ahi[mt][0], ahi[mt][1], ahi[mt][2], ahi[mt][3], aa);
            uint32_t al = a_addr(xlo, mw * 32 + mt * 16, kb, lane);
            ldsm_x4(alo[mt][0], alo[mt][1], alo[mt][2], alo[mt][3], al);
        }
#pragma unroll
        for (int p = 0; p < 2; p++) {
            uint32_t ba = b_addr(whi, nw * 32 + p * 16, kb, lane);
            ldsm_x4(bhi[2*p][0], bhi[2*p][1], bhi[2*p+1][0], bhi[2*p+1][1], ba);
            uint32_t bb = b_addr(wlo, nw * 32 + p * 16, kb, lane);
            ldsm_x4(blo[2*p][0], blo[2*p][1], blo[2*p+1][0], blo[2*p+1][1], bb);
        }
#pragma unroll
        for (int mt = 0; mt < 2; mt++)
#pragma unroll
            for (int nt = 0; nt < 4; nt++) {
                mma_bf16(acc[mt][nt], ahi[mt], bhi[nt][0], bhi[nt][1]);
                mma_bf16(acc[mt][nt], ahi[mt], blo[nt][0], blo[nt][1]);
                mma_bf16(acc[mt][nt], alo[mt], bhi[nt][0], bhi[nt][1]);
            }
    }
}

__device__ __forceinline__ void stage_frags(float* stage, int mw, int nw, int lane,
                                            const float acc[2][4][4]) {
    const int rsub = lane >> 2;
    const int csub = (lane & 3) * 2;
#pragma unroll
    for (int mt = 0; mt < 2; mt++)
#pragma unroll
        for (int nt = 0; nt < 4; nt++) {
            int row = mw * 32 + mt * 16 + rsub;
            int col = nw * 32 + nt * 8 + csub;
            *(float2*)(stage + row * STAGE_STRIDE + col) =
                make_float2(acc[mt][nt][0], acc[mt][nt][1]);
            *(float2*)(stage + (row + 8) * STAGE_STRIDE + col) =
                make_float2(acc[mt][nt][2], acc[mt][nt][3]);
        }
}

// LN stats for one staged row segment (re-read; h recomputed in write pass)
__device__ __forceinline__ void ln_stats(const float* row, const float* bias, int qh,
                                         float& mean, float& rs) {
    float s = 0.f, q = 0.f;
#pragma unroll
    for (int i = 0; i < 8; i++) {
        float4 v = ((const float4*)row)[i];
        const int c = qh * 32 + i * 4;
        float h0 = fmaxf(v.x + bias[c + 0], 0.f);
        float h1 = fmaxf(v.y + bias[c + 1], 0.f);
        float h2 = fmaxf(v.z + bias[c + 2], 0.f);
        float h3 = fmaxf(v.w + bias[c + 3], 0.f);
        s += h0 + h1 + h2 + h3;
        q = fmaf(h0, h0, q); q = fmaf(h1, h1, q);
        q = fmaf(h2, h2, q); q = fmaf(h3, h3, q);
    }
    s += __shfl_xor_sync(0xffffffffu, s, 1);
    q += __shfl_xor_sync(0xffffffffu, q, 1);
    s += __shfl_xor_sync(0xffffffffu, s, 2);
    q += __shfl_xor_sync(0xffffffffu, q, 2);
    mean = s * (1.f / DIM);
    float var = q * (1.f / DIM) - mean * mean + 1e-9f;
    rs = rsqrtf(var);
}

// ---------------------------------------------------------------------------
// Merged branch kernel: out = LNs(relu(Xself Ws^T + bs)) + LNn(relu(Xneigh Wn^T + bn))
// Phase A: Ws/Xself -> acc_s (regs). Phase B (same SMEM region): Wn/Xneigh -> acc_n.
// Single epilogue: stage both, LN both (stats pass + write pass), one out write.
// ---------------------------------------------------------------------------
__global__ void __launch_bounds__(256, 2) mma_merged(
    const float* __restrict__ X,
    const uint4* __restrict__ wshi, const uint4* __restrict__ wslo,
    const uint4* __restrict__ wnhi, const uint4* __restrict__ wnlo,
    const uint4* __restrict__ gxhi, const uint4* __restrict__ gxlo,
    const float* __restrict__ b_self, const float* __restrict__ b_neigh,
    const float* __restrict__ scale, const float* __restrict__ offset,
    float* __restrict__ out)
{
    extern __shared__ char smem[];
    const uint32_t sb = smem_u32(smem);
    const int tid  = threadIdx.x;
    const int wid  = tid >> 5;
    const int lane = tid & 31;
    const int mw   = wid & 1;
    const int nw   = wid >> 1;
    const int gbase = blockIdx.x * TILE_M;

    float* sB0 = (float*)(smem + OFF_CONST);        // b_self   128
    float* sB1 = sB0 + 128;                          // b_neigh  128
    float* sS  = sB1 + 128;                          // scale    256
    float* sO  = sS + 256;                           // offset   256

    // ---- Phase A: Ws + Xself ----
    for (int i = tid; i < 2048; i += 256) {
        ((uint4*)(smem + OFF_W))[i]         = wshi[i];
        ((uint4*)(smem + OFF_W + 32768))[i] = wslo[i];
    }
    for (int i = tid; i < 1024; i += 256) {
        int r = i >> 4, k0 = (i & 15) << 3;
        int gr = gbase + r; if (gr >= N_NODES) gr = N_NODES - 1;
        split_store8(X + (size_t)gr * DIM + k0, smem + OFF_X, smem + OFF_X + 16384, r, k0);
    }
    if (tid < 32)        ((float4*)sB0)[tid]      = ((const float4*)b_self)[tid];
    else if (tid < 64)   ((float4*)sB1)[tid - 32] = ((const float4*)b_neigh)[tid - 32];
    else if (tid < 128)  ((float4*)sS)[tid - 64]  = ((const float4*)scale)[tid - 64];
    else if (tid < 192)  ((float4*)sO)[tid - 128] = ((const float4*)offset)[tid - 128];
    __syncthreads();

    float acc_s[2][4][4];
    run_gemm(sb, mw, nw, lane, acc_s);
    __syncthreads();   // phase A reads done

    // ---- Phase B: Wn + Xneigh (pre-swizzled copies) ----
    for (int i = tid; i < 2048; i += 256) {
        ((uint4*)(smem + OFF_W))[i]         = wnhi[i];
        ((uint4*)(smem + OFF_W + 32768))[i] = wnlo[i];
    }
    {
        const uint4* xh = gxhi + (size_t)blockIdx.x * 1024;
        const uint4* xl = gxlo + (size_t)blockIdx.x * 1024;
        for (int i = tid; i < 1024; i += 256) {
            ((uint4*)(smem + OFF_X))[i]         = xh[i];
            ((uint4*)(smem + OFF_X + 16384))[i] = xl[i];
        }
    }
    __syncthreads();

    float acc_n[2][4][4];
    run_gemm(sb, mw, nw, lane, acc_n);
    __syncthreads();   // phase B reads done; stages may overlay

    // ---- Epilogue ----
    float* stageA = (float*)(smem + OFF_STAGE_A);
    float* stageB = (float*)(smem + OFF_STAGE_B);
    stage_frags(stageA, mw, nw, lane, acc_s);
    stage_frags(stageB, mw, nw, lane, acc_n);
    __syncthreads();

    {
        const int r  = tid >> 2;
        const int qh = tid & 3;
        const float* rowA = stageA + r * STAGE_STRIDE + qh * 32;
        const float* rowB = stageB + r * STAGE_STRIDE + qh * 32;

        float meanA, rsA, meanB, rsB;
        ln_stats(rowA, sB0, qh, meanA, rsA);
        ln_stats(rowB, sB1, qh, meanB, rsB);

        const int g = gbase + r;
        if (g < N_NODES) {
            float4* op = (float4*)(out + (size_t)g * DIM + qh * 32);
#pragma unroll
            for (int i = 0; i < 8; i++) {
                float4 va = ((const float4*)rowA)[i];
                float4 vb = ((const float4*)rowB)[i];
                const int c = qh * 32 + i * 4;
                float4 rv;
                rv.x = (fmaxf(va.x + sB0[c+0], 0.f) - meanA) * rsA * sS[c+0]       + sO[c+0]
                     + (fmaxf(vb.x + sB1[c+0], 0.f) - meanB) * rsB * sS[128+c+0]   + sO[128+c+0];
                rv.y = (fmaxf(va.y + sB0[c+1], 0.f) - meanA) * rsA * sS[c+1]       + sO[c+1]
                     + (fmaxf(vb.y + sB1[c+1], 0.f) - meanB) * rsB * sS[128+c+1]   + sO[128+c+1];
                rv.z = (fmaxf(va.z + sB0[c+2], 0.f) - meanA) * rsA * sS[c+2]       + sO[c+2]
                     + (fmaxf(vb.z + sB1[c+2], 0.f) - meanB) * rsB * sS[128+c+2]   + sO[128+c+2];
                rv.w = (fmaxf(va.w + sB0[c+3], 0.f) - meanA) * rsA * sS[c+3]       + sO[c+3]
                     + (fmaxf(vb.w + sB1[c+3], 0.f) - meanB) * rsB * sS[128+c+3]   + sO[128+c+3];
                op[i] = rv;
            }
        }
    }
}

// ---------------------------------------------------------------------------
struct ForkResources {
    cudaStream_t s2  = nullptr;
    cudaEvent_t  ev1 = nullptr, ev2 = nullptr;
    bool ok = false;
    ForkResources() {
        if (cudaStreamCreateWithFlags(&s2, cudaStreamNonBlocking) != cudaSuccess) return;
        if (cudaEventCreateWithFlags(&ev1, cudaEventDisableTiming) != cudaSuccess) return;
        if (cudaEventCreateWithFlags(&ev2, cudaEventDisableTiming) != cudaSuccess) return;
        ok = true;
    }
};
static ForkResources g_fork;

// ---------------------------------------------------------------------------
// stream0: count -> bsum -> scan_bsums -> offsets -> fill -> gather -\
// s2:      wconv -----------------------------------------------------join-> mma_merged
// ---------------------------------------------------------------------------
extern "C" void kernel_launch(void* const* d_in, const int* in_sizes, int n_in,
                              void* d_out, int out_size) {
    const float* feat_in  = (const float*)d_in[0];
    const int*   edge_row = (const int*)  d_in[1];
    const int*   edge_col = (const int*)  d_in[2];
    const float* edge_val = (const float*)d_in[3];
    const float* W_self   = (const float*)d_in[4];
    const float* b_self   = (const float*)d_in[5];
    const float* W_neigh  = (const float*)d_in[6];
    const float* b_neigh  = (const float*)d_in[7];
    const float* scale    = (const float*)d_in[8];
    const float* offset   = (const float*)d_in[9];
    float* out = (float*)d_out;

    int *cnt, *ofs, *cur, *bsum, *bbase;
    int2 *pack;
    void *wshi, *wslo, *wnhi, *wnlo, *xhi, *xlo;
    cudaGetSymbolAddress((void**)&cnt,   g_cnt);
    cudaGetSymbolAddress((void**)&ofs,   g_ofs);
    cudaGetSymbolAddress((void**)&cur,   g_cur);
    cudaGetSymbolAddress((void**)&pack,  g_pack);
    cudaGetSymbolAddress((void**)&bsum,  g_bsum);
    cudaGetSymbolAddress((void**)&bbase, g_bbase);
    cudaGetSymbolAddress(&wshi, g_wshi);
    cudaGetSymbolAddress(&wslo, g_wslo);
    cudaGetSymbolAddress(&wnhi, g_wnhi);
    cudaGetSymbolAddress(&wnlo, g_wnlo);
    cudaGetSymbolAddress(&xhi,  g_xhi);
    cudaGetSymbolAddress(&xlo,  g_xlo);

    cudaFuncSetAttribute(mma_merged,
                         cudaFuncAttributeMaxDynamicSharedMemorySize, MERGED_SMEM);

    const int eb4 = (N_EDGES / 4 + 255) / 256;
    const int gb  = (N_TILES * TILE_M * 32 + 255) / 256;   // warp per node (incl. tail)

    if (g_fork.ok) {
        cudaEventRecord(g_fork.ev1, 0);
        cudaStreamWaitEvent(g_fork.s2, g_fork.ev1, 0);

        wconv_kernel<<<16, 256, 0, g_fork.s2>>>(W_self, W_neigh);

        count_kernel<<<eb4, 256>>>((const int4*)edge_row, cnt);
        bsum_kernel<<<NB_SCAN, SCAN_BS>>>(cnt, bsum);
        scan_bsums<<<1, 256>>>(bsum, bbase);
        offsets_kernel<<<NB_SCAN, SCAN_BS>>>(cnt, bbase, ofs, cur);
        fill_kernel<<<eb4, 256>>>((const int4*)edge_row, (const int4*)edge_col,
                                  (const float4*)edge_val, cur, pack);
        gather_kernel<<<gb, 256>>>((const float4*)feat_in, ofs, pack);

        cudaEventRecord(g_fork.ev2, g_fork.s2);
        cudaStreamWaitEvent(0, g_fork.ev2, 0);

        mma_merged<<<N_TILES, 256, MERGED_SMEM>>>(
            feat_in, (const uint4*)wshi, (const uint4*)wslo,
            (const uint4*)wnhi, (const uint4*)wnlo,
            (const uint4*)xhi, (const uint4*)xlo,
            b_self, b_neigh, scale, offset, out);
    } else {
        wconv_kernel<<<16, 256>>>(W_self, W_neigh);
        count_kernel<<<eb4, 256>>>((const int4*)edge_row, cnt);
        bsum_kernel<<<NB_SCAN, SCAN_BS>>>(cnt, bsum);
        scan_bsums<<<1, 256>>>(bsum, bbase);
        offsets_kernel<<<NB_SCAN, SCAN_BS>>>(cnt, bbase, ofs, cur);
        fill_kernel<<<eb4, 256>>>((const int4*)edge_row, (const int4*)edge_col,
                                  (const float4*)edge_val, cur, pack);
        gather_kernel<<<gb, 256>>>((const float4*)feat_in, ofs, pack);
        mma_merged<<<N_TILES, 256, MERGED_SMEM>>>(
            feat_in, (const uint4*)wshi, (const uint4*)wslo,
            (const uint4*)wnhi, (const uint4*)wnlo,
            (const uint4*)xhi, (const uint4*)xlo,
            b_self, b_neigh, scale, offset, out);
    }
}

// round 17
// speedup vs baseline: 1.1297x; 1.0059x over previous
#include <cuda_runtime.h>
#include <cuda_bf16.h>
#include <cstdint>

#define N_NODES 50000
#define N_EDGES 800000
#define DIM     128

#define TILE_M   64
#define N_TILES  ((N_NODES + TILE_M - 1) / TILE_M)   // 782
#define MM_THREADS 512

// ---------------- merged-kernel SMEM layout (bytes) ------------------------
#define OFF_X     0
#define OFF_W     32768
#define OFF_CONST 98304        // b_self 512 | b_neigh 512 | scale 1024 | offset 1024
#define MERGED_SMEM (98304 + 3072)
#define STAGE_STRIDE 132
#define OFF_STAGE_A 0
#define OFF_STAGE_B 34816      // 64*132*4 = 33792, padded

// ---------------- scan partition ------------------------------------------
#define SCAN_BS   256
#define NB_SCAN   ((N_NODES + SCAN_BS - 1) / SCAN_BS)   // 196

// ---------------- scratch (__device__ globals; zero-initialized) ----------
__device__ int   g_cnt[N_NODES];                      // self-cleaned in offsets
__device__ int   g_ofs[N_NODES + 1];
__device__ int   g_cur[N_NODES];
__device__ int2  g_pack[N_EDGES];                     // (col, val bits)
__device__ int   g_bsum[NB_SCAN];
__device__ __align__(16) char g_wshi[32768];
__device__ __align__(16) char g_wslo[32768];
__device__ __align__(16) char g_wnhi[32768];
__device__ __align__(16) char g_wnlo[32768];
__device__ __align__(16) char g_xhi[(size_t)N_TILES * 16384];   // 12.8MB
__device__ __align__(16) char g_xlo[(size_t)N_TILES * 16384];

// ---------------------------------------------------------------------------
__global__ void count_kernel(const int4* __restrict__ erow4, int* __restrict__ cnt) {
    int e = blockIdx.x * blockDim.x + threadIdx.x;
    if (e < N_EDGES / 4) {
        int4 r = erow4[e];
        atomicAdd(&cnt[r.x], 1);
        atomicAdd(&cnt[r.y], 1);
        atomicAdd(&cnt[r.z], 1);
        atomicAdd(&cnt[r.w], 1);
    }
}

__global__ void __launch_bounds__(SCAN_BS) bsum_kernel(const int* __restrict__ cnt,
                                                       int* __restrict__ bsum) {
    __shared__ int red[SCAN_BS / 32];
    int i = blockIdx.x * SCAN_BS + threadIdx.x;
    int v = (i < N_NODES) ? cnt[i] : 0;
#pragma unroll
    for (int o = 16; o; o >>= 1) v += __shfl_xor_sync(0xffffffffu, v, o);
    if ((threadIdx.x & 31) == 0) red[threadIdx.x >> 5] = v;
    __syncthreads();
    if (threadIdx.x == 0) {
        int s = 0;
#pragma unroll
        for (int w = 0; w < SCAN_BS / 32; w++) s += red[w];
        bsum[blockIdx.x] = s;
    }
}

// offsets: computes own block base from bsum (196 values) + in-block scan.
// Self-cleans cnt for the next graph replay.
__global__ void __launch_bounds__(SCAN_BS) offsets_kernel(
    int* __restrict__ cnt, const int* __restrict__ bsum,
    int* __restrict__ ofs, int* __restrict__ cur)
{
    __shared__ int sh[SCAN_BS];
    __shared__ int red[SCAN_BS / 32];
    const int t = threadIdx.x;
    const int b = blockIdx.x;
    const int i = b * SCAN_BS + t;

    // block base = sum of bsum[j] for j < b
    int contrib = (t < b && t < NB_SCAN) ? bsum[t] : 0;
#pragma unroll
    for (int o = 16; o; o >>= 1) contrib += __shfl_xor_sync(0xffffffffu, contrib, o);
    if ((t & 31) == 0) red[t >> 5] = contrib;

    int v = (i < N_NODES) ? cnt[i] : 0;
    if (i < N_NODES) cnt[i] = 0;
    sh[t] = v;
    __syncthreads();

    int base = 0;
#pragma unroll
    for (int w = 0; w < SCAN_BS / 32; w++) base += red[w];

#pragma unroll
    for (int o = 1; o < SCAN_BS; o <<= 1) {
        int u = (t >= o) ? sh[t - o] : 0;
        __syncthreads();
        sh[t] += u;
        __syncthreads();
    }
    if (i < N_NODES) {
        int excl = base + sh[t] - v;
        ofs[i] = excl;
        cur[i] = excl;
    }
    if (i == N_NODES - 1) ofs[N_NODES] = N_EDGES;
}

__global__ void fill_kernel(const int4* __restrict__ erow4, const int4* __restrict__ ecol4,
                            const float4* __restrict__ eval4,
                            int* __restrict__ cur, int2* __restrict__ pack) {
    int e = blockIdx.x * blockDim.x + threadIdx.x;
    if (e >= N_EDGES / 4) return;
    int4   r = erow4[e];
    int4   c = ecol4[e];
    float4 v = eval4[e];
    int p0 = atomicAdd(&cur[r.x], 1);
    int p1 = atomicAdd(&cur[r.y], 1);
    int p2 = atomicAdd(&cur[r.z], 1);
    int p3 = atomicAdd(&cur[r.w], 1);
    pack[p0] = make_int2(c.x, __float_as_int(v.x));
    pack[p1] = make_int2(c.y, __float_as_int(v.y));
    pack[p2] = make_int2(c.z, __float_as_int(v.z));
    pack[p3] = make_int2(c.w, __float_as_int(v.w));
}

// ---------------------------------------------------------------------------
__device__ __forceinline__ uint32_t bt_off(int r, int k0) {
    return (uint32_t)(r * 256 + ((((k0 >> 3) ^ (r & 7)) & 15) << 4));
}
__device__ __forceinline__ void split_store8(const float* src, char* hi_base, char* lo_base,
                                             int r, int k0) {
    float4 a = ((const float4*)src)[0];
    float4 b = ((const float4*)src)[1];
    float v[8] = {a.x, a.y, a.z, a.w, b.x, b.y, b.z, b.w};
    uint32_t hp[4], lp[4];
#pragma unroll
    for (int e = 0; e < 4; e++) {
        __nv_bfloat16 h0 = __float2bfloat16(v[2 * e]);
        __nv_bfloat16 h1 = __float2bfloat16(v[2 * e + 1]);
        __nv_bfloat16 l0 = __float2bfloat16(v[2 * e]     - __bfloat162float(h0));
        __nv_bfloat16 l1 = __float2bfloat16(v[2 * e + 1] - __bfloat162float(h1));
        __nv_bfloat162 hh = __halves2bfloat162(h0, h1);
        __nv_bfloat162 ll = __halves2bfloat162(l0, l1);
        hp[e] = *(uint32_t*)&hh;
        lp[e] = *(uint32_t*)&ll;
    }
    uint32_t o = bt_off(r, k0);
    *(uint4*)(hi_base + o) = make_uint4(hp[0], hp[1], hp[2], hp[3]);
    *(uint4*)(lo_base + o) = make_uint4(lp[0], lp[1], lp[2], lp[3]);
}

__global__ void __launch_bounds__(256) wconv_kernel(const float* __restrict__ Ws,
                                                    const float* __restrict__ Wn) {
    int i = blockIdx.x * blockDim.x + threadIdx.x;
    if (i >= 4096) return;
    int sel = i >> 11;
    int j   = i & 2047;
    int r = j >> 4, k0 = (j & 15) << 3;
    const float* W = sel ? Wn : Ws;
    char* hi = sel ? g_wnhi : g_wshi;
    char* lo = sel ? g_wnlo : g_wslo;
    split_store8(W + r * DIM + k0, hi, lo, r, k0);
}

// ---------------------------------------------------------------------------
// gather: WARP per node, unroll x8; writes bf16 hi/lo in the per-tile layout.
// ---------------------------------------------------------------------------
__global__ void __launch_bounds__(256, 4) gather_kernel(
    const float4* __restrict__ feat4, const int* __restrict__ ofs,
    const int2* __restrict__ pack)
{
    const int node = (blockIdx.x * blockDim.x + threadIdx.x) >> 5;
    const int lane = threadIdx.x & 31;
    if (node >= N_TILES * TILE_M) return;

    float4 acc = make_float4(0.f, 0.f, 0.f, 0.f);
    if (node < N_NODES) {
        const int beg = ofs[node];
        const int end = ofs[node + 1];
        int e = beg;
        for (; e + 8 <= end; e += 8) {
            int2 p[8];
            float4 x[8];
#pragma unroll
            for (int i = 0; i < 8; i++) p[i] = pack[e + i];
#pragma unroll
            for (int i = 0; i < 8; i++) x[i] = feat4[(size_t)p[i].x * 32 + lane];
#pragma unroll
            for (int i = 0; i < 8; i++) {
                float v = __int_as_float(p[i].y);
                acc.x = fmaf(v, x[i].x, acc.x); acc.y = fmaf(v, x[i].y, acc.y);
                acc.z = fmaf(v, x[i].z, acc.z); acc.w = fmaf(v, x[i].w, acc.w);
            }
        }
        for (; e + 4 <= end; e += 4) {
            int2 p[4];
            float4 x[4];
#pragma unroll
            for (int i = 0; i < 4; i++) p[i] = pack[e + i];
#pragma unroll
            for (int i = 0; i < 4; i++) x[i] = feat4[(size_t)p[i].x * 32 + lane];
#pragma unroll
            for (int i = 0; i < 4; i++) {
                float v = __int_as_float(p[i].y);
                acc.x = fmaf(v, x[i].x, acc.x); acc.y = fmaf(v, x[i].y, acc.y);
                acc.z = fmaf(v, x[i].z, acc.z); acc.w = fmaf(v, x[i].w, acc.w);
            }
        }
        for (; e < end; e++) {
            int2 p = pack[e];
            float v = __int_as_float(p.y);
            float4 x = feat4[(size_t)p.x * 32 + lane];
            acc.x = fmaf(v, x.x, acc.x); acc.y = fmaf(v, x.y, acc.y);
            acc.z = fmaf(v, x.z, acc.z); acc.w = fmaf(v, x.w, acc.w);
        }
    }

    __nv_bfloat16 h0 = __float2bfloat16(acc.x), h1 = __float2bfloat16(acc.y);
    __nv_bfloat16 h2 = __float2bfloat16(acc.z), h3 = __float2bfloat16(acc.w);
    __nv_bfloat16 l0 = __float2bfloat16(acc.x - __bfloat162float(h0));
    __nv_bfloat16 l1 = __float2bfloat16(acc.y - __bfloat162float(h1));
    __nv_bfloat16 l2 = __float2bfloat16(acc.z - __bfloat162float(h2));
    __nv_bfloat16 l3 = __float2bfloat16(acc.w - __bfloat162float(h3));
    __nv_bfloat162 hA = __halves2bfloat162(h0, h1), hB = __halves2bfloat162(h2, h3);
    __nv_bfloat162 lA = __halves2bfloat162(l0, l1), lB = __halves2bfloat162(l2, l3);

    const int tile = node >> 6, r = node & 63;
    const uint32_t off = (uint32_t)r * 256
                       + ((((lane >> 1) ^ (r & 7)) & 15) << 4) + ((lane & 1) << 3);
    char* hb = g_xhi + (size_t)tile * 16384;
    char* lb = g_xlo + (size_t)tile * 16384;
    *(uint2*)(hb + off) = make_uint2(*(uint32_t*)&hA, *(uint32_t*)&hB);
    *(uint2*)(lb + off) = make_uint2(*(uint32_t*)&lA, *(uint32_t*)&lB);
}

// ---------------------------------------------------------------------------
__device__ __forceinline__ uint32_t smem_u32(const void* p) {
    uint32_t a;
    asm("{ .reg .u64 t; cvta.to.shared.u64 t, %1; cvt.u32.u64 %0, t; }" : "=r"(a) : "l"(p));
    return a;
}
__device__ __forceinline__ void ldsm_x4(uint32_t& r0, uint32_t& r1,
                                        uint32_t& r2, uint32_t& r3, uint32_t a) {
    asm volatile("ldmatrix.sync.aligned.m8n8.x4.shared.b16 {%0,%1,%2,%3}, [%4];"
                 : "=r"(r0), "=r"(r1), "=r"(r2), "=r"(r3) : "r"(a));
}
__device__ __forceinline__ void mma_bf16(float* c, const uint32_t* a,
                                         uint32_t b0, uint32_t b1) {
    asm volatile("mma.sync.aligned.m16n8k16.row.col.f32.bf16.bf16.f32 "
                 "{%0,%1,%2,%3}, {%4,%5,%6,%7}, {%8,%9}, {%0,%1,%2,%3};"
                 : "+f"(c[0]), "+f"(c[1]), "+f"(c[2]), "+f"(c[3])
                 : "r"(a[0]), "r"(a[1]), "r"(a[2]), "r"(a[3]), "r"(b0), "r"(b1));
}
__device__ __forceinline__ uint32_t a_addr(uint32_t base, int m0, int kb, int lane) {
    int row = m0 + (lane & 15);
    int chunk = (kb >> 3) + (lane >> 4);
    return base + row * 256 + (((chunk ^ (row & 7)) & 15) << 4);
}
__device__ __forceinline__ uint32_t b_addr(uint32_t base, int n0, int kb, int lane) {
    int row = n0 + (lane & 7) + ((lane >> 4) << 3);
    int chunk = (kb >> 3) + ((lane >> 3) & 1);
    return base + row * 256 + (((chunk ^ (row & 7)) & 15) << 4);
}

// mainloop for 16-warp layout: warp tile 16(m) x 32(n); acc[4][4]
__device__ __forceinline__ void run_gemm16(uint32_t sb, int mw, int nw, int lane,
                                           float acc[4][4]) {
    const uint32_t xhi = sb + OFF_X,  xlo = sb + OFF_X + 16384;
    const uint32_t whi = sb + OFF_W,  wlo = sb + OFF_W + 32768;
#pragma unroll
    for (int nt = 0; nt < 4; nt++)
#pragma unroll
        for (int e = 0; e < 4; e++) acc[nt][e] = 0.f;

#pragma unroll
    for (int kb8 = 0; kb8 < 8; kb8++) {
        const int kb = kb8 * 16;
        uint32_t ahi[4], alo[4], bhi[4][2], blo[4][2];
        {
            uint32_t aa = a_addr(xhi, mw * 16, kb, lane);
            ldsm_x4(ahi[0], ahi[1], ahi[2], ahi[3], aa);
            uint32_t al = a_addr(xlo, mw * 16, kb, lane);
            ldsm_x4(alo[0], alo[1], alo[2], alo[3], al);
        }
#pragma unroll
        for (int p = 0; p < 2; p++) {
            uint32_t ba = b_addr(whi, nw * 32 + p * 16, kb, lane);
            ldsm_x4(bhi[2*p][0], bhi[2*p][1], bhi[2*p+1][0], bhi[2*p+1][1], ba);
            uint32_t bb = b_addr(wlo, nw * 32 + p * 16, kb, lane);
            ldsm_x4(blo[2*p][0], blo[2*p][1], blo[2*p+1][0], blo[2*p+1][1], bb);
        }
#pragma unroll
        for (int nt = 0; nt < 4; nt++) {
            mma_bf16(acc[nt], ahi, bhi[nt][0], bhi[nt][1]);
            mma_bf16(acc[nt], ahi, blo[nt][0], blo[nt][1]);
            mma_bf16(acc[nt], alo, bhi[nt][0], bhi[nt][1]);
        }
    }
}

__device__ __forceinline__ void stage_frags16(float* stage, int mw, int nw, int lane,
                                              const float acc[4][4]) {
    const int rsub = lane >> 2;
    const int csub = (lane & 3) * 2;
#pragma unroll
    for (int nt = 0; nt < 4; nt++) {
        int row = mw * 16 + rsub;
        int col = nw * 32 + nt * 8 + csub;
        *(float2*)(stage + row * STAGE_STRIDE + col) = make_float2(acc[nt][0], acc[nt][1]);
        *(float2*)(stage + (row + 8) * STAGE_STRIDE + col) = make_float2(acc[nt][2], acc[nt][3]);
    }
}

// LN stats over a 16-col segment; reduce across 8 threads (xor 1,2,4)
__device__ __forceinline__ void ln_stats16(const float* row, const float* bias, int qh,
                                           float& mean, float& rs) {
    float s = 0.f, q = 0.f;
#pragma unroll
    for (int i = 0; i < 4; i++) {
        float4 v = ((const float4*)row)[i];
        const int c = qh * 16 + i * 4;
        float h0 = fmaxf(v.x + bias[c + 0], 0.f);
        float h1 = fmaxf(v.y + bias[c + 1], 0.f);
        float h2 = fmaxf(v.z + bias[c + 2], 0.f);
        float h3 = fmaxf(v.w + bias[c + 3], 0.f);
        s += h0 + h1 + h2 + h3;
        q = fmaf(h0, h0, q); q = fmaf(h1, h1, q);
        q = fmaf(h2, h2, q); q = fmaf(h3, h3, q);
    }
    s += __shfl_xor_sync(0xffffffffu, s, 1);
    q += __shfl_xor_sync(0xffffffffu, q, 1);
    s += __shfl_xor_sync(0xffffffffu, s, 2);
    q += __shfl_xor_sync(0xffffffffu, q, 2);
    s += __shfl_xor_sync(0xffffffffu, s, 4);
    q += __shfl_xor_sync(0xffffffffu, q, 4);
    mean = s * (1.f / DIM);
    float var = q * (1.f / DIM) - mean * mean + 1e-9f;
    rs = rsqrtf(var);
}

// ---------------------------------------------------------------------------
// Merged branch kernel (512 threads, 16 warps: mw=wid&3, nw=wid>>2):
// out = LNs(relu(Xself Ws^T + bs)) + LNn(relu(Xneigh Wn^T + bn))
// ---------------------------------------------------------------------------
__global__ void __launch_bounds__(MM_THREADS, 2) mma_merged(
    const float* __restrict__ X,
    const uint4* __restrict__ wshi, const uint4* __restrict__ wslo,
    const uint4* __restrict__ wnhi, const uint4* __restrict__ wnlo,
    const uint4* __restrict__ gxhi, const uint4* __restrict__ gxlo,
    const float* __restrict__ b_self, const float* __restrict__ b_neigh,
    const float* __restrict__ scale, const float* __restrict__ offset,
    float* __restrict__ out)
{
    extern __shared__ char smem[];
    const uint32_t sb = smem_u32(smem);
    const int tid  = threadIdx.x;
    const int wid  = tid >> 5;
    const int lane = tid & 31;
    const int mw   = wid & 3;
    const int nw   = wid >> 2;
    const int gbase = blockIdx.x * TILE_M;

    float* sB0 = (float*)(smem + OFF_CONST);
    float* sB1 = sB0 + 128;
    float* sS  = sB1 + 128;
    float* sO  = sS + 256;

    // ---- Phase A: Ws + Xself ----
    for (int i = tid; i < 2048; i += MM_THREADS) {
        ((uint4*)(smem + OFF_W))[i]         = wshi[i];
        ((uint4*)(smem + OFF_W + 32768))[i] = wslo[i];
    }
    for (int i = tid; i < 1024; i += MM_THREADS) {
        int r = i >> 4, k0 = (i & 15) << 3;
        int gr = gbase + r; if (gr >= N_NODES) gr = N_NODES - 1;
        split_store8(X + (size_t)gr * DIM + k0, smem + OFF_X, smem + OFF_X + 16384, r, k0);
    }
    if (tid < 32)        ((float4*)sB0)[tid]      = ((const float4*)b_self)[tid];
    else if (tid < 64)   ((float4*)sB1)[tid - 32] = ((const float4*)b_neigh)[tid - 32];
    else if (tid < 128)  ((float4*)sS)[tid - 64]  = ((const float4*)scale)[tid - 64];
    else if (tid < 192)  ((float4*)sO)[tid - 128] = ((const float4*)offset)[tid - 128];
    __syncthreads();

    float acc_s[4][4];
    run_gemm16(sb, mw, nw, lane, acc_s);
    __syncthreads();

    // ---- Phase B: Wn + Xneigh (pre-swizzled copies) ----
    for (int i = tid; i < 2048; i += MM_THREADS) {
        ((uint4*)(smem + OFF_W))[i]         = wnhi[i];
        ((uint4*)(smem + OFF_W + 32768))[i] = wnlo[i];
    }
    {
        const uint4* xh = gxhi + (size_t)blockIdx.x * 1024;
        const uint4* xl = gxlo + (size_t)blockIdx.x * 1024;
        for (int i = tid; i < 1024; i += MM_THREADS) {
            ((uint4*)(smem + OFF_X))[i]         = xh[i];
            ((uint4*)(smem + OFF_X + 16384))[i] = xl[i];
        }
    }
    __syncthreads();

    float acc_n[4][4];
    run_gemm16(sb, mw, nw, lane, acc_n);
    __syncthreads();

    // ---- Epilogue ----
    float* stageA = (float*)(smem + OFF_STAGE_A);
    float* stageB = (float*)(smem + OFF_STAGE_B);
    stage_frags16(stageA, mw, nw, lane, acc_s);
    stage_frags16(stageB, mw, nw, lane, acc_n);
    __syncthreads();

    {
        const int r  = tid >> 3;              // 0..63
        const int qh = tid & 7;               // 16-col segment
        const float* rowA = stageA + r * STAGE_STRIDE + qh * 16;
        const float* rowB = stageB + r * STAGE_STRIDE + qh * 16;

        float meanA, rsA, meanB, rsB;
        ln_stats16(rowA, sB0, qh, meanA, rsA);
        ln_stats16(rowB, sB1, qh, meanB, rsB);

        const int g = gbase + r;
        if (g < N_NODES) {
            float4* op = (float4*)(out + (size_t)g * DIM + qh * 16);
#pragma unroll
            for (int i = 0; i < 4; i++) {
                float4 va = ((const float4*)rowA)[i];
                float4 vb = ((const float4*)rowB)[i];
                const int c = qh * 16 + i * 4;
                float4 rv;
                rv.x = (fmaxf(va.x + sB0[c+0], 0.f) - meanA) * rsA * sS[c+0]     + sO[c+0]
                     + (fmaxf(vb.x + sB1[c+0], 0.f) - meanB) * rsB * sS[128+c+0] + sO[128+c+0];
                rv.y = (fmaxf(va.y + sB0[c+1], 0.f) - meanA) * rsA * sS[c+1]     + sO[c+1]
                     + (fmaxf(vb.y + sB1[c+1], 0.f) - meanB) * rsB * sS[128+c+1] + sO[128+c+1];
                rv.z = (fmaxf(va.z + sB0[c+2], 0.f) - meanA) * rsA * sS[c+2]     + sO[c+2]
                     + (fmaxf(vb.z + sB1[c+2], 0.f) - meanB) * rsB * sS[128+c+2] + sO[128+c+2];
                rv.w = (fmaxf(va.w + sB0[c+3], 0.f) - meanA) * rsA * sS[c+3]     + sO[c+3]
                     + (fmaxf(vb.w + sB1[c+3], 0.f) - meanB) * rsB * sS[128+c+3] + sO[128+c+3];
                op[i] = rv;
            }
        }
    }
}

// ---------------------------------------------------------------------------
struct ForkResources {
    cudaStream_t s2  = nullptr;
    cudaEvent_t  ev1 = nullptr, ev2 = nullptr;
    bool ok = false;
    ForkResources() {
        if (cudaStreamCreateWithFlags(&s2, cudaStreamNonBlocking) != cudaSuccess) return;
        if (cudaEventCreateWithFlags(&ev1, cudaEventDisableTiming) != cudaSuccess) return;
        if (cudaEventCreateWithFlags(&ev2, cudaEventDisableTiming) != cudaSuccess) return;
        ok = true;
    }
};
static ForkResources g_fork;

// ---------------------------------------------------------------------------
// stream0: count -> bsum -> offsets -> fill -> gather -\
// s2:      wconv ----------------------------------------join-> mma_merged
// ---------------------------------------------------------------------------
extern "C" void kernel_launch(void* const* d_in, const int* in_sizes, int n_in,
                              void* d_out, int out_size) {
    const float* feat_in  = (const float*)d_in[0];
    const int*   edge_row = (const int*)  d_in[1];
    const int*   edge_col = (const int*)  d_in[2];
    const float* edge_val = (const float*)d_in[3];
    const float* W_self   = (const float*)d_in[4];
    const float* b_self   = (const float*)d_in[5];
    const float* W_neigh  = (const float*)d_in[6];
    const float* b_neigh  = (const float*)d_in[7];
    const float* scale    = (const float*)d_in[8];
    const float* offset   = (const float*)d_in[9];
    float* out = (float*)d_out;

    int *cnt, *ofs, *cur, *bsum;
    int2 *pack;
    void *wshi, *wslo, *wnhi, *wnlo, *xhi, *xlo;
    cudaGetSymbolAddress((void**)&cnt,   g_cnt);
    cudaGetSymbolAddress((void**)&ofs,   g_ofs);
    cudaGetSymbolAddress((void**)&cur,   g_cur);
    cudaGetSymbolAddress((void**)&pack,  g_pack);
    cudaGetSymbolAddress((void**)&bsum,  g_bsum);
    cudaGetSymbolAddress(&wshi, g_wshi);
    cudaGetSymbolAddress(&wslo, g_wslo);
    cudaGetSymbolAddress(&wnhi, g_wnhi);
    cudaGetSymbolAddress(&wnlo, g_wnlo);
    cudaGetSymbolAddress(&xhi,  g_xhi);
    cudaGetSymbolAddress(&xlo,  g_xlo);

    cudaFuncSetAttribute(mma_merged,
                         cudaFuncAttributeMaxDynamicSharedMemorySize, MERGED_SMEM);

    const int eb4 = (N_EDGES / 4 + 255) / 256;
    const int gb  = (N_TILES * TILE_M * 32 + 255) / 256;

    if (g_fork.ok) {
        cudaEventRecord(g_fork.ev1, 0);
        cudaStreamWaitEvent(g_fork.s2, g_fork.ev1, 0);

        wconv_kernel<<<16, 256, 0, g_fork.s2>>>(W_self, W_neigh);

        count_kernel<<<eb4, 256>>>((const int4*)edge_row, cnt);
        bsum_kernel<<<NB_SCAN, SCAN_BS>>>(cnt, bsum);
        offsets_kernel<<<NB_SCAN, SCAN_BS>>>(cnt, bsum, ofs, cur);
        fill_kernel<<<eb4, 256>>>((const int4*)edge_row, (const int4*)edge_col,
                                  (const float4*)edge_val, cur, pack);
        gather_kernel<<<gb, 256>>>((const float4*)feat_in, ofs, pack);

        cudaEventRecord(g_fork.ev2, g_fork.s2);
        cudaStreamWaitEvent(0, g_fork.ev2, 0);

        mma_merged<<<N_TILES, MM_THREADS, MERGED_SMEM>>>(
            feat_in, (const uint4*)wshi, (const uint4*)wslo,
            (const uint4*)wnhi, (const uint4*)wnlo,
            (const uint4*)xhi, (const uint4*)xlo,
            b_self, b_neigh, scale, offset, out);
    } else {
        wconv_kernel<<<16, 256>>>(W_self, W_neigh);
        count_kernel<<<eb4, 256>>>((const int4*)edge_row, cnt);
        bsum_kernel<<<NB_SCAN, SCAN_BS>>>(cnt, bsum);
        offsets_kernel<<<NB_SCAN, SCAN_BS>>>(cnt, bsum, ofs, cur);
        fill_kernel<<<eb4, 256>>>((const int4*)edge_row, (const int4*)edge_col,
                                  (const float4*)edge_val, cur, pack);
        gather_kernel<<<gb, 256>>>((const float4*)feat_in, ofs, pack);
        mma_merged<<<N_TILES, MM_THREADS, MERGED_SMEM>>>(
            feat_in, (const uint4*)wshi, (const uint4*)wslo,
            (const uint4*)wnhi, (const uint4*)wnlo,
            (const uint4*)xhi, (const uint4*)xlo,
            b_self, b_neigh, scale, offset, out);
    }
}